// round 1
// baseline (speedup 1.0000x reference)
#include <cuda_runtime.h>

#define HIDDEN 1024
#define HEADS 16
#define HDIM 64
#define BATCH 2
#define SEQ 2048
#define ROWS (BATCH*SEQ)          // 4096
#define BH (BATCH*HEADS)          // 32
#define SCROWS (BH*SEQ)           // 65536
#define NEGV -1.0e9f

// Scratch (allocation-free rule: __device__ globals)
__device__ float g_q[BH*SEQ*HDIM];
__device__ float g_k[BH*SEQ*HDIM];
__device__ float g_v[BH*SEQ*HDIM];
__device__ float g_ctx[ROWS*HIDDEN];
__device__ float g_y[ROWS*HIDDEN];
__device__ float g_rmax[SCROWS];
__device__ float g_rinv[SCROWS];

// ---------------------------------------------------------------------------
// QKV projection: C = x @ W + b, scattered to [B,H,S,D]. 128x128x8 SGEMM.
// ---------------------------------------------------------------------------
__global__ __launch_bounds__(256) void qkv_gemm(
    const float* __restrict__ x,
    const float* __restrict__ Wq, const float* __restrict__ bq,
    const float* __restrict__ Wk, const float* __restrict__ bk,
    const float* __restrict__ Wv, const float* __restrict__ bv)
{
    const float* W; const float* bias; float* out;
    if (blockIdx.z == 0)      { W = Wq; bias = bq; out = g_q; }
    else if (blockIdx.z == 1) { W = Wk; bias = bk; out = g_k; }
    else                      { W = Wv; bias = bv; out = g_v; }

    __shared__ float As[8][128];
    __shared__ float Bs[8][128];
    const int tid = threadIdx.x;
    const int tx = tid & 15, ty = tid >> 4;
    const int m0 = blockIdx.y * 128, n0 = blockIdx.x * 128;
    const int arow = tid >> 1, acol = (tid & 1) * 4;
    const int brow = tid >> 5, bcol = (tid & 31) * 4;

    float acc[8][8];
#pragma unroll
    for (int i = 0; i < 8; i++)
#pragma unroll
        for (int j = 0; j < 8; j++) acc[i][j] = 0.f;

    for (int k0 = 0; k0 < HIDDEN; k0 += 8) {
        float4 a = *(const float4*)&x[(size_t)(m0 + arow) * HIDDEN + k0 + acol];
        As[acol + 0][arow] = a.x; As[acol + 1][arow] = a.y;
        As[acol + 2][arow] = a.z; As[acol + 3][arow] = a.w;
        *(float4*)&Bs[brow][bcol] =
            *(const float4*)&W[(size_t)(k0 + brow) * HIDDEN + n0 + bcol];
        __syncthreads();
#pragma unroll
        for (int kk = 0; kk < 8; kk++) {
            float ra[8], rb[8];
#pragma unroll
            for (int i = 0; i < 8; i++) ra[i] = As[kk][ty * 8 + i];
#pragma unroll
            for (int j = 0; j < 8; j++) rb[j] = Bs[kk][tx * 8 + j];
#pragma unroll
            for (int i = 0; i < 8; i++)
#pragma unroll
                for (int j = 0; j < 8; j++) acc[i][j] = fmaf(ra[i], rb[j], acc[i][j]);
        }
        __syncthreads();
    }

#pragma unroll
    for (int i = 0; i < 8; i++) {
        int row = m0 + ty * 8 + i;
        int b = row >> 11, s = row & (SEQ - 1);
#pragma unroll
        for (int j4 = 0; j4 < 2; j4++) {
            int col = n0 + tx * 8 + j4 * 4;
            int h = col >> 6, d = col & 63;
            float4 v;
            v.x = acc[i][j4*4+0] + bias[col+0];
            v.y = acc[i][j4*4+1] + bias[col+1];
            v.z = acc[i][j4*4+2] + bias[col+2];
            v.w = acc[i][j4*4+3] + bias[col+3];
            *(float4*)&out[(((size_t)(b*HEADS + h))*SEQ + s)*HDIM + d] = v;
        }
    }
}

// ---------------------------------------------------------------------------
// Output projection + residual: g_y = g_ctx @ Wo + bo + x
// ---------------------------------------------------------------------------
__global__ __launch_bounds__(256) void proj_gemm(
    const float* __restrict__ Wo, const float* __restrict__ bo,
    const float* __restrict__ x)
{
    __shared__ float As[8][128];
    __shared__ float Bs[8][128];
    const int tid = threadIdx.x;
    const int tx = tid & 15, ty = tid >> 4;
    const int m0 = blockIdx.y * 128, n0 = blockIdx.x * 128;
    const int arow = tid >> 1, acol = (tid & 1) * 4;
    const int brow = tid >> 5, bcol = (tid & 31) * 4;

    float acc[8][8];
#pragma unroll
    for (int i = 0; i < 8; i++)
#pragma unroll
        for (int j = 0; j < 8; j++) acc[i][j] = 0.f;

    for (int k0 = 0; k0 < HIDDEN; k0 += 8) {
        float4 a = *(const float4*)&g_ctx[(size_t)(m0 + arow) * HIDDEN + k0 + acol];
        As[acol + 0][arow] = a.x; As[acol + 1][arow] = a.y;
        As[acol + 2][arow] = a.z; As[acol + 3][arow] = a.w;
        *(float4*)&Bs[brow][bcol] =
            *(const float4*)&Wo[(size_t)(k0 + brow) * HIDDEN + n0 + bcol];
        __syncthreads();
#pragma unroll
        for (int kk = 0; kk < 8; kk++) {
            float ra[8], rb[8];
#pragma unroll
            for (int i = 0; i < 8; i++) ra[i] = As[kk][ty * 8 + i];
#pragma unroll
            for (int j = 0; j < 8; j++) rb[j] = Bs[kk][tx * 8 + j];
#pragma unroll
            for (int i = 0; i < 8; i++)
#pragma unroll
                for (int j = 0; j < 8; j++) acc[i][j] = fmaf(ra[i], rb[j], acc[i][j]);
        }
        __syncthreads();
    }

#pragma unroll
    for (int i = 0; i < 8; i++) {
        int row = m0 + ty * 8 + i;
#pragma unroll
        for (int j4 = 0; j4 < 2; j4++) {
            int col = n0 + tx * 8 + j4 * 4;
            float4 xv = *(const float4*)&x[(size_t)row * HIDDEN + col];
            float4 bv = *(const float4*)&bo[col];
            float4 v;
            v.x = acc[i][j4*4+0] + bv.x + xv.x;
            v.y = acc[i][j4*4+1] + bv.y + xv.y;
            v.z = acc[i][j4*4+2] + bv.z + xv.z;
            v.w = acc[i][j4*4+3] + bv.w + xv.w;
            *(float4*)&g_y[(size_t)row * HIDDEN + col] = v;
        }
    }
}

// ---------------------------------------------------------------------------
// scores = (Q @ K^T)/8, masked, written to output. 64x64 tile per block.
// smem tiles stored d-major (transposed) with 16B XOR swizzle for
// conflict-free float4 access in both store and compute phases.
// ---------------------------------------------------------------------------
__global__ __launch_bounds__(256) void scores_kernel(
    const int* __restrict__ am, float* __restrict__ sc_out)
{
    __shared__ float QsT[64][64];
    __shared__ float KsT[64][64];
    const int tid = threadIdx.x;
    const int tx = tid & 15, ty = tid >> 4;
    const int k0 = blockIdx.x * 64, q0 = blockIdx.y * 64;
    const int bh = blockIdx.z;
    const float* qp = g_q + (size_t)bh * SEQ * HDIM;
    const float* kp = g_k + (size_t)bh * SEQ * HDIM;

#pragma unroll
    for (int it = 0; it < 4; it++) {
        int idx = it * 256 + tid;
        int d = idx & 63, rg = idx >> 6;
        float4 qv, kv;
        qv.x = qp[(size_t)(q0 + rg*4 + 0) * HDIM + d];
        qv.y = qp[(size_t)(q0 + rg*4 + 1) * HDIM + d];
        qv.z = qp[(size_t)(q0 + rg*4 + 2) * HDIM + d];
        qv.w = qp[(size_t)(q0 + rg*4 + 3) * HDIM + d];
        kv.x = kp[(size_t)(k0 + rg*4 + 0) * HDIM + d];
        kv.y = kp[(size_t)(k0 + rg*4 + 1) * HDIM + d];
        kv.z = kp[(size_t)(k0 + rg*4 + 2) * HDIM + d];
        kv.w = kp[(size_t)(k0 + rg*4 + 3) * HDIM + d];
        *(float4*)&QsT[d][4 * (rg ^ (d & 15))] = qv;
        *(float4*)&KsT[d][4 * (rg ^ (d & 15))] = kv;
    }
    __syncthreads();

    float acc[4][4];
#pragma unroll
    for (int i = 0; i < 4; i++)
#pragma unroll
        for (int j = 0; j < 4; j++) acc[i][j] = 0.f;

#pragma unroll
    for (int d = 0; d < 64; d++) {
        float4 a = *(const float4*)&QsT[d][4 * (ty ^ (d & 15))];
        float4 b = *(const float4*)&KsT[d][4 * (tx ^ (d & 15))];
        float ra[4] = {a.x, a.y, a.z, a.w};
        float rb[4] = {b.x, b.y, b.z, b.w};
#pragma unroll
        for (int i = 0; i < 4; i++)
#pragma unroll
            for (int j = 0; j < 4; j++) acc[i][j] = fmaf(ra[i], rb[j], acc[i][j]);
    }

    const int b_ = bh >> 4;
#pragma unroll
    for (int i = 0; i < 4; i++) {
        int q = q0 + ty * 4 + i;
        int kk = k0 + tx * 4;
        int4 m4 = *(const int4*)&am[((size_t)b_ * SEQ + q) * SEQ + kk];
        float4 v;
        v.x = m4.x ? acc[i][0] * 0.125f : NEGV;
        v.y = m4.y ? acc[i][1] * 0.125f : NEGV;
        v.z = m4.z ? acc[i][2] * 0.125f : NEGV;
        v.w = m4.w ? acc[i][3] * 0.125f : NEGV;
        *(float4*)&sc_out[((size_t)bh * SEQ + q) * SEQ + kk] = v;
    }
}

// ---------------------------------------------------------------------------
// Per-row softmax stats: rowmax and 1/sum(exp(s-max)) over 2048 elements.
// ---------------------------------------------------------------------------
__global__ __launch_bounds__(256) void stats_kernel(const float* __restrict__ sc)
{
    const int r = blockIdx.x;
    const float4* p = (const float4*)(sc + (size_t)r * SEQ);
    const int tid = threadIdx.x;
    __shared__ float red[8];

    float4 a = p[tid];
    float4 b = p[tid + 256];
    float m = fmaxf(fmaxf(fmaxf(a.x, a.y), fmaxf(a.z, a.w)),
                    fmaxf(fmaxf(b.x, b.y), fmaxf(b.z, b.w)));
#pragma unroll
    for (int o = 16; o; o >>= 1) m = fmaxf(m, __shfl_xor_sync(0xffffffffu, m, o));
    if ((tid & 31) == 0) red[tid >> 5] = m;
    __syncthreads();
    if (tid < 32) {
        float t = (tid < 8) ? red[tid] : -3.4e38f;
#pragma unroll
        for (int o = 4; o; o >>= 1) t = fmaxf(t, __shfl_xor_sync(0xffffffffu, t, o));
        if (tid == 0) red[0] = t;
    }
    __syncthreads();
    m = red[0];
    __syncthreads();

    float s = __expf(a.x - m) + __expf(a.y - m) + __expf(a.z - m) + __expf(a.w - m)
            + __expf(b.x - m) + __expf(b.y - m) + __expf(b.z - m) + __expf(b.w - m);
#pragma unroll
    for (int o = 16; o; o >>= 1) s += __shfl_xor_sync(0xffffffffu, s, o);
    if ((tid & 31) == 0) red[tid >> 5] = s;
    __syncthreads();
    if (tid < 32) {
        float t = (tid < 8) ? red[tid] : 0.f;
#pragma unroll
        for (int o = 4; o; o >>= 1) t += __shfl_xor_sync(0xffffffffu, t, o);
        if (tid == 0) { g_rmax[r] = m; g_rinv[r] = 1.f / t; }
    }
}

// ---------------------------------------------------------------------------
// ctx = softmax(scores) @ V, probs computed on the fly; ctx stored [B,S,HIDDEN].
// ---------------------------------------------------------------------------
__global__ __launch_bounds__(256) void ctx_kernel(const float* __restrict__ sc)
{
    __shared__ float PsT[64][64];
    __shared__ float Vs[64][64];
    const int tid = threadIdx.x;
    const int tx = tid & 15, ty = tid >> 4;
    const int q0 = blockIdx.x * 64;
    const int bh = blockIdx.y;
    const int b_ = bh >> 4, h = bh & 15;
    const float* vp = g_v + (size_t)bh * SEQ * HDIM;
    const float* scp = sc + (size_t)bh * SEQ * SEQ;

    float acc[4][4];
#pragma unroll
    for (int i = 0; i < 4; i++)
#pragma unroll
        for (int j = 0; j < 4; j++) acc[i][j] = 0.f;

    for (int kk0 = 0; kk0 < SEQ; kk0 += 64) {
#pragma unroll
        for (int it = 0; it < 4; it++) {
            int idx = it * 256 + tid;
            int kl = idx & 63, qg = idx >> 6;
            int qr = q0 + qg * 4;
            float4 pv;
            pv.x = __expf(scp[(size_t)(qr+0)*SEQ + kk0 + kl] - g_rmax[bh*SEQ + qr+0]) * g_rinv[bh*SEQ + qr+0];
            pv.y = __expf(scp[(size_t)(qr+1)*SEQ + kk0 + kl] - g_rmax[bh*SEQ + qr+1]) * g_rinv[bh*SEQ + qr+1];
            pv.z = __expf(scp[(size_t)(qr+2)*SEQ + kk0 + kl] - g_rmax[bh*SEQ + qr+2]) * g_rinv[bh*SEQ + qr+2];
            pv.w = __expf(scp[(size_t)(qr+3)*SEQ + kk0 + kl] - g_rmax[bh*SEQ + qr+3]) * g_rinv[bh*SEQ + qr+3];
            *(float4*)&PsT[kl][4 * (qg ^ (kl & 15))] = pv;
        }
#pragma unroll
        for (int it = 0; it < 4; it++) {
            int idx = it * 256 + tid;
            int kr = idx >> 4, c4 = idx & 15;
            *(float4*)&Vs[kr][c4 * 4] =
                *(const float4*)&vp[(size_t)(kk0 + kr) * HDIM + c4 * 4];
        }
        __syncthreads();
#pragma unroll
        for (int k = 0; k < 64; k++) {
            float4 a = *(const float4*)&PsT[k][4 * (ty ^ (k & 15))];
            float4 b = *(const float4*)&Vs[k][tx * 4];
            float ra[4] = {a.x, a.y, a.z, a.w};
            float rb[4] = {b.x, b.y, b.z, b.w};
#pragma unroll
            for (int i = 0; i < 4; i++)
#pragma unroll
                for (int j = 0; j < 4; j++) acc[i][j] = fmaf(ra[i], rb[j], acc[i][j]);
        }
        __syncthreads();
    }

#pragma unroll
    for (int i = 0; i < 4; i++) {
        int q = q0 + ty * 4 + i;
        float4 v = {acc[i][0], acc[i][1], acc[i][2], acc[i][3]};
        *(float4*)&g_ctx[((size_t)(b_ * SEQ + q)) * HIDDEN + h * HDIM + tx * 4] = v;
    }
}

// ---------------------------------------------------------------------------
// LayerNorm over last dim of g_y -> out
// ---------------------------------------------------------------------------
__global__ __launch_bounds__(256) void ln_kernel(
    const float* __restrict__ gamma, const float* __restrict__ beta,
    float* __restrict__ out)
{
    const int row = blockIdx.x;
    const int tid = threadIdx.x;
    __shared__ float red[8];
    const float4* p = (const float4*)(g_y + (size_t)row * HIDDEN);
    float4 v = p[tid];

    float s = v.x + v.y + v.z + v.w;
#pragma unroll
    for (int o = 16; o; o >>= 1) s += __shfl_xor_sync(0xffffffffu, s, o);
    if ((tid & 31) == 0) red[tid >> 5] = s;
    __syncthreads();
    if (tid < 32) {
        float t = (tid < 8) ? red[tid] : 0.f;
#pragma unroll
        for (int o = 4; o; o >>= 1) t += __shfl_xor_sync(0xffffffffu, t, o);
        if (tid == 0) red[0] = t;
    }
    __syncthreads();
    float mu = red[0] * (1.f / HIDDEN);
    __syncthreads();

    float dx = v.x - mu, dy = v.y - mu, dz = v.z - mu, dw = v.w - mu;
    float s2 = dx*dx + dy*dy + dz*dz + dw*dw;
#pragma unroll
    for (int o = 16; o; o >>= 1) s2 += __shfl_xor_sync(0xffffffffu, s2, o);
    if ((tid & 31) == 0) red[tid >> 5] = s2;
    __syncthreads();
    if (tid < 32) {
        float t = (tid < 8) ? red[tid] : 0.f;
#pragma unroll
        for (int o = 4; o; o >>= 1) t += __shfl_xor_sync(0xffffffffu, t, o);
        if (tid == 0) red[0] = t;
    }
    __syncthreads();
    float var = red[0] * (1.f / HIDDEN);
    float rs = rsqrtf(var + 1e-12f);

    float4 gg = ((const float4*)gamma)[tid];
    float4 bb = ((const float4*)beta)[tid];
    float4 o4;
    o4.x = dx * rs * gg.x + bb.x;
    o4.y = dy * rs * gg.y + bb.y;
    o4.z = dz * rs * gg.z + bb.z;
    o4.w = dw * rs * gg.w + bb.w;
    ((float4*)(out + (size_t)row * HIDDEN))[tid] = o4;
}

// ---------------------------------------------------------------------------
extern "C" void kernel_launch(void* const* d_in, const int* in_sizes, int n_in,
                              void* d_out, int out_size)
{
    const float* x  = (const float*)d_in[0];
    const int*   am = (const int*)d_in[1];
    const float* Wq = (const float*)d_in[2];  const float* bq = (const float*)d_in[3];
    const float* Wk = (const float*)d_in[4];  const float* bk = (const float*)d_in[5];
    const float* Wv = (const float*)d_in[6];  const float* bv = (const float*)d_in[7];
    const float* Wo = (const float*)d_in[8];  const float* bo = (const float*)d_in[9];
    const float* lg = (const float*)d_in[10]; const float* lb = (const float*)d_in[11];

    float* out = (float*)d_out;
    float* sc  = out + (size_t)ROWS * HIDDEN;   // scores follow `out` in the tuple

    qkv_gemm<<<dim3(8, 32, 3), 256>>>(x, Wq, bq, Wk, bk, Wv, bv);
    scores_kernel<<<dim3(32, 32, 32), 256>>>(am, sc);
    stats_kernel<<<SCROWS, 256>>>(sc);
    ctx_kernel<<<dim3(32, 32), 256>>>(sc);
    proj_gemm<<<dim3(8, 32), 256>>>(Wo, bo, x);
    ln_kernel<<<ROWS, 256>>>(lg, lb, out);
}

// round 2
// speedup vs baseline: 1.0002x; 1.0002x over previous
#include <cuda_runtime.h>

#define HIDDEN 1024
#define HEADS 16
#define HDIM 64
#define BATCH 2
#define SEQ 2048
#define ROWS (BATCH*SEQ)          // 4096
#define BH (BATCH*HEADS)          // 32
#define SCROWS (BH*SEQ)           // 65536
#define NEGV -1.0e9f

// Scratch (allocation-free rule: __device__ globals)
__device__ float g_q[BH*SEQ*HDIM];
__device__ float g_k[BH*SEQ*HDIM];
__device__ float g_v[BH*SEQ*HDIM];
__device__ float g_ctx[ROWS*HIDDEN];
__device__ float g_y[ROWS*HIDDEN];
__device__ float g_rmax[SCROWS];
__device__ float g_rinv[SCROWS];

// ---------------------------------------------------------------------------
// QKV projection: C = x @ W + b, scattered to [B,H,S,D]. 128x128x8 SGEMM.
// ---------------------------------------------------------------------------
__global__ __launch_bounds__(256) void qkv_gemm(
    const float* __restrict__ x,
    const float* __restrict__ Wq, const float* __restrict__ bq,
    const float* __restrict__ Wk, const float* __restrict__ bk,
    const float* __restrict__ Wv, const float* __restrict__ bv)
{
    const float* W; const float* bias; float* out;
    if (blockIdx.z == 0)      { W = Wq; bias = bq; out = g_q; }
    else if (blockIdx.z == 1) { W = Wk; bias = bk; out = g_k; }
    else                      { W = Wv; bias = bv; out = g_v; }

    __shared__ float As[8][128];
    __shared__ float Bs[8][128];
    const int tid = threadIdx.x;
    const int tx = tid & 15, ty = tid >> 4;
    const int m0 = blockIdx.y * 128, n0 = blockIdx.x * 128;
    const int arow = tid >> 1, acol = (tid & 1) * 4;
    const int brow = tid >> 5, bcol = (tid & 31) * 4;

    float acc[8][8];
#pragma unroll
    for (int i = 0; i < 8; i++)
#pragma unroll
        for (int j = 0; j < 8; j++) acc[i][j] = 0.f;

    for (int k0 = 0; k0 < HIDDEN; k0 += 8) {
        float4 a = *(const float4*)&x[(size_t)(m0 + arow) * HIDDEN + k0 + acol];
        As[acol + 0][arow] = a.x; As[acol + 1][arow] = a.y;
        As[acol + 2][arow] = a.z; As[acol + 3][arow] = a.w;
        *(float4*)&Bs[brow][bcol] =
            *(const float4*)&W[(size_t)(k0 + brow) * HIDDEN + n0 + bcol];
        __syncthreads();
#pragma unroll
        for (int kk = 0; kk < 8; kk++) {
            float ra[8], rb[8];
#pragma unroll
            for (int i = 0; i < 8; i++) ra[i] = As[kk][ty * 8 + i];
#pragma unroll
            for (int j = 0; j < 8; j++) rb[j] = Bs[kk][tx * 8 + j];
#pragma unroll
            for (int i = 0; i < 8; i++)
#pragma unroll
                for (int j = 0; j < 8; j++) acc[i][j] = fmaf(ra[i], rb[j], acc[i][j]);
        }
        __syncthreads();
    }

#pragma unroll
    for (int i = 0; i < 8; i++) {
        int row = m0 + ty * 8 + i;
        int b = row >> 11, s = row & (SEQ - 1);
#pragma unroll
        for (int j4 = 0; j4 < 2; j4++) {
            int col = n0 + tx * 8 + j4 * 4;
            int h = col >> 6, d = col & 63;
            float4 v;
            v.x = acc[i][j4*4+0] + bias[col+0];
            v.y = acc[i][j4*4+1] + bias[col+1];
            v.z = acc[i][j4*4+2] + bias[col+2];
            v.w = acc[i][j4*4+3] + bias[col+3];
            *(float4*)&out[(((size_t)(b*HEADS + h))*SEQ + s)*HDIM + d] = v;
        }
    }
}

// ---------------------------------------------------------------------------
// Output projection + residual: g_y = g_ctx @ Wo + bo + x
// ---------------------------------------------------------------------------
__global__ __launch_bounds__(256) void proj_gemm(
    const float* __restrict__ Wo, const float* __restrict__ bo,
    const float* __restrict__ x)
{
    __shared__ float As[8][128];
    __shared__ float Bs[8][128];
    const int tid = threadIdx.x;
    const int tx = tid & 15, ty = tid >> 4;
    const int m0 = blockIdx.y * 128, n0 = blockIdx.x * 128;
    const int arow = tid >> 1, acol = (tid & 1) * 4;
    const int brow = tid >> 5, bcol = (tid & 31) * 4;

    float acc[8][8];
#pragma unroll
    for (int i = 0; i < 8; i++)
#pragma unroll
        for (int j = 0; j < 8; j++) acc[i][j] = 0.f;

    for (int k0 = 0; k0 < HIDDEN; k0 += 8) {
        float4 a = *(const float4*)&g_ctx[(size_t)(m0 + arow) * HIDDEN + k0 + acol];
        As[acol + 0][arow] = a.x; As[acol + 1][arow] = a.y;
        As[acol + 2][arow] = a.z; As[acol + 3][arow] = a.w;
        *(float4*)&Bs[brow][bcol] =
            *(const float4*)&Wo[(size_t)(k0 + brow) * HIDDEN + n0 + bcol];
        __syncthreads();
#pragma unroll
        for (int kk = 0; kk < 8; kk++) {
            float ra[8], rb[8];
#pragma unroll
            for (int i = 0; i < 8; i++) ra[i] = As[kk][ty * 8 + i];
#pragma unroll
            for (int j = 0; j < 8; j++) rb[j] = Bs[kk][tx * 8 + j];
#pragma unroll
            for (int i = 0; i < 8; i++)
#pragma unroll
                for (int j = 0; j < 8; j++) acc[i][j] = fmaf(ra[i], rb[j], acc[i][j]);
        }
        __syncthreads();
    }

#pragma unroll
    for (int i = 0; i < 8; i++) {
        int row = m0 + ty * 8 + i;
#pragma unroll
        for (int j4 = 0; j4 < 2; j4++) {
            int col = n0 + tx * 8 + j4 * 4;
            float4 xv = *(const float4*)&x[(size_t)row * HIDDEN + col];
            float4 bv = *(const float4*)&bo[col];
            float4 v;
            v.x = acc[i][j4*4+0] + bv.x + xv.x;
            v.y = acc[i][j4*4+1] + bv.y + xv.y;
            v.z = acc[i][j4*4+2] + bv.z + xv.z;
            v.w = acc[i][j4*4+3] + bv.w + xv.w;
            *(float4*)&g_y[(size_t)row * HIDDEN + col] = v;
        }
    }
}

// ---------------------------------------------------------------------------
// scores = (Q @ K^T)/8, masked, written to output. 64x64 tile per block.
// smem tiles stored d-major (transposed) with 16B XOR swizzle for
// conflict-free float4 access in both store and compute phases.
// ---------------------------------------------------------------------------
__global__ __launch_bounds__(256) void scores_kernel(
    const int* __restrict__ am, float* __restrict__ sc_out)
{
    __shared__ float QsT[64][64];
    __shared__ float KsT[64][64];
    const int tid = threadIdx.x;
    const int tx = tid & 15, ty = tid >> 4;
    const int k0 = blockIdx.x * 64, q0 = blockIdx.y * 64;
    const int bh = blockIdx.z;
    const float* qp = g_q + (size_t)bh * SEQ * HDIM;
    const float* kp = g_k + (size_t)bh * SEQ * HDIM;

#pragma unroll
    for (int it = 0; it < 4; it++) {
        int idx = it * 256 + tid;
        int d = idx & 63, rg = idx >> 6;
        float4 qv, kv;
        qv.x = qp[(size_t)(q0 + rg*4 + 0) * HDIM + d];
        qv.y = qp[(size_t)(q0 + rg*4 + 1) * HDIM + d];
        qv.z = qp[(size_t)(q0 + rg*4 + 2) * HDIM + d];
        qv.w = qp[(size_t)(q0 + rg*4 + 3) * HDIM + d];
        kv.x = kp[(size_t)(k0 + rg*4 + 0) * HDIM + d];
        kv.y = kp[(size_t)(k0 + rg*4 + 1) * HDIM + d];
        kv.z = kp[(size_t)(k0 + rg*4 + 2) * HDIM + d];
        kv.w = kp[(size_t)(k0 + rg*4 + 3) * HDIM + d];
        *(float4*)&QsT[d][4 * (rg ^ (d & 15))] = qv;
        *(float4*)&KsT[d][4 * (rg ^ (d & 15))] = kv;
    }
    __syncthreads();

    float acc[4][4];
#pragma unroll
    for (int i = 0; i < 4; i++)
#pragma unroll
        for (int j = 0; j < 4; j++) acc[i][j] = 0.f;

#pragma unroll
    for (int d = 0; d < 64; d++) {
        float4 a = *(const float4*)&QsT[d][4 * (ty ^ (d & 15))];
        float4 b = *(const float4*)&KsT[d][4 * (tx ^ (d & 15))];
        float ra[4] = {a.x, a.y, a.z, a.w};
        float rb[4] = {b.x, b.y, b.z, b.w};
#pragma unroll
        for (int i = 0; i < 4; i++)
#pragma unroll
            for (int j = 0; j < 4; j++) acc[i][j] = fmaf(ra[i], rb[j], acc[i][j]);
    }

    const int b_ = bh >> 4;
#pragma unroll
    for (int i = 0; i < 4; i++) {
        int q = q0 + ty * 4 + i;
        int kk = k0 + tx * 4;
        int4 m4 = *(const int4*)&am[((size_t)b_ * SEQ + q) * SEQ + kk];
        float4 v;
        v.x = m4.x ? acc[i][0] * 0.125f : NEGV;
        v.y = m4.y ? acc[i][1] * 0.125f : NEGV;
        v.z = m4.z ? acc[i][2] * 0.125f : NEGV;
        v.w = m4.w ? acc[i][3] * 0.125f : NEGV;
        *(float4*)&sc_out[((size_t)bh * SEQ + q) * SEQ + kk] = v;
    }
}

// ---------------------------------------------------------------------------
// Per-row softmax stats: rowmax and 1/sum(exp(s-max)) over 2048 elements.
// ---------------------------------------------------------------------------
__global__ __launch_bounds__(256) void stats_kernel(const float* __restrict__ sc)
{
    const int r = blockIdx.x;
    const float4* p = (const float4*)(sc + (size_t)r * SEQ);
    const int tid = threadIdx.x;
    __shared__ float red[8];

    float4 a = p[tid];
    float4 b = p[tid + 256];
    float m = fmaxf(fmaxf(fmaxf(a.x, a.y), fmaxf(a.z, a.w)),
                    fmaxf(fmaxf(b.x, b.y), fmaxf(b.z, b.w)));
#pragma unroll
    for (int o = 16; o; o >>= 1) m = fmaxf(m, __shfl_xor_sync(0xffffffffu, m, o));
    if ((tid & 31) == 0) red[tid >> 5] = m;
    __syncthreads();
    if (tid < 32) {
        float t = (tid < 8) ? red[tid] : -3.4e38f;
#pragma unroll
        for (int o = 4; o; o >>= 1) t = fmaxf(t, __shfl_xor_sync(0xffffffffu, t, o));
        if (tid == 0) red[0] = t;
    }
    __syncthreads();
    m = red[0];
    __syncthreads();

    float s = __expf(a.x - m) + __expf(a.y - m) + __expf(a.z - m) + __expf(a.w - m)
            + __expf(b.x - m) + __expf(b.y - m) + __expf(b.z - m) + __expf(b.w - m);
#pragma unroll
    for (int o = 16; o; o >>= 1) s += __shfl_xor_sync(0xffffffffu, s, o);
    if ((tid & 31) == 0) red[tid >> 5] = s;
    __syncthreads();
    if (tid < 32) {
        float t = (tid < 8) ? red[tid] : 0.f;
#pragma unroll
        for (int o = 4; o; o >>= 1) t += __shfl_xor_sync(0xffffffffu, t, o);
        if (tid == 0) { g_rmax[r] = m; g_rinv[r] = 1.f / t; }
    }
}

// ---------------------------------------------------------------------------
// ctx = softmax(scores) @ V, probs computed on the fly; ctx stored [B,S,HIDDEN].
// ---------------------------------------------------------------------------
__global__ __launch_bounds__(256) void ctx_kernel(const float* __restrict__ sc)
{
    __shared__ float PsT[64][64];
    __shared__ float Vs[64][64];
    const int tid = threadIdx.x;
    const int tx = tid & 15, ty = tid >> 4;
    const int q0 = blockIdx.x * 64;
    const int bh = blockIdx.y;
    const int b_ = bh >> 4, h = bh & 15;
    const float* vp = g_v + (size_t)bh * SEQ * HDIM;
    const float* scp = sc + (size_t)bh * SEQ * SEQ;

    float acc[4][4];
#pragma unroll
    for (int i = 0; i < 4; i++)
#pragma unroll
        for (int j = 0; j < 4; j++) acc[i][j] = 0.f;

    for (int kk0 = 0; kk0 < SEQ; kk0 += 64) {
#pragma unroll
        for (int it = 0; it < 4; it++) {
            int idx = it * 256 + tid;
            int kl = idx & 63, qg = idx >> 6;
            int qr = q0 + qg * 4;
            float4 pv;
            pv.x = __expf(scp[(size_t)(qr+0)*SEQ + kk0 + kl] - g_rmax[bh*SEQ + qr+0]) * g_rinv[bh*SEQ + qr+0];
            pv.y = __expf(scp[(size_t)(qr+1)*SEQ + kk0 + kl] - g_rmax[bh*SEQ + qr+1]) * g_rinv[bh*SEQ + qr+1];
            pv.z = __expf(scp[(size_t)(qr+2)*SEQ + kk0 + kl] - g_rmax[bh*SEQ + qr+2]) * g_rinv[bh*SEQ + qr+2];
            pv.w = __expf(scp[(size_t)(qr+3)*SEQ + kk0 + kl] - g_rmax[bh*SEQ + qr+3]) * g_rinv[bh*SEQ + qr+3];
            *(float4*)&PsT[kl][4 * (qg ^ (kl & 15))] = pv;
        }
#pragma unroll
        for (int it = 0; it < 4; it++) {
            int idx = it * 256 + tid;
            int kr = idx >> 4, c4 = idx & 15;
            *(float4*)&Vs[kr][c4 * 4] =
                *(const float4*)&vp[(size_t)(kk0 + kr) * HDIM + c4 * 4];
        }
        __syncthreads();
#pragma unroll
        for (int k = 0; k < 64; k++) {
            float4 a = *(const float4*)&PsT[k][4 * (ty ^ (k & 15))];
            float4 b = *(const float4*)&Vs[k][tx * 4];
            float ra[4] = {a.x, a.y, a.z, a.w};
            float rb[4] = {b.x, b.y, b.z, b.w};
#pragma unroll
            for (int i = 0; i < 4; i++)
#pragma unroll
                for (int j = 0; j < 4; j++) acc[i][j] = fmaf(ra[i], rb[j], acc[i][j]);
        }
        __syncthreads();
    }

#pragma unroll
    for (int i = 0; i < 4; i++) {
        int q = q0 + ty * 4 + i;
        float4 v = {acc[i][0], acc[i][1], acc[i][2], acc[i][3]};
        *(float4*)&g_ctx[((size_t)(b_ * SEQ + q)) * HIDDEN + h * HDIM + tx * 4] = v;
    }
}

// ---------------------------------------------------------------------------
// LayerNorm over last dim of g_y -> out
// ---------------------------------------------------------------------------
__global__ __launch_bounds__(256) void ln_kernel(
    const float* __restrict__ gamma, const float* __restrict__ beta,
    float* __restrict__ out)
{
    const int row = blockIdx.x;
    const int tid = threadIdx.x;
    __shared__ float red[8];
    const float4* p = (const float4*)(g_y + (size_t)row * HIDDEN);
    float4 v = p[tid];

    float s = v.x + v.y + v.z + v.w;
#pragma unroll
    for (int o = 16; o; o >>= 1) s += __shfl_xor_sync(0xffffffffu, s, o);
    if ((tid & 31) == 0) red[tid >> 5] = s;
    __syncthreads();
    if (tid < 32) {
        float t = (tid < 8) ? red[tid] : 0.f;
#pragma unroll
        for (int o = 4; o; o >>= 1) t += __shfl_xor_sync(0xffffffffu, t, o);
        if (tid == 0) red[0] = t;
    }
    __syncthreads();
    float mu = red[0] * (1.f / HIDDEN);
    __syncthreads();

    float dx = v.x - mu, dy = v.y - mu, dz = v.z - mu, dw = v.w - mu;
    float s2 = dx*dx + dy*dy + dz*dz + dw*dw;
#pragma unroll
    for (int o = 16; o; o >>= 1) s2 += __shfl_xor_sync(0xffffffffu, s2, o);
    if ((tid & 31) == 0) red[tid >> 5] = s2;
    __syncthreads();
    if (tid < 32) {
        float t = (tid < 8) ? red[tid] : 0.f;
#pragma unroll
        for (int o = 4; o; o >>= 1) t += __shfl_xor_sync(0xffffffffu, t, o);
        if (tid == 0) red[0] = t;
    }
    __syncthreads();
    float var = red[0] * (1.f / HIDDEN);
    float rs = rsqrtf(var + 1e-12f);

    float4 gg = ((const float4*)gamma)[tid];
    float4 bb = ((const float4*)beta)[tid];
    float4 o4;
    o4.x = dx * rs * gg.x + bb.x;
    o4.y = dy * rs * gg.y + bb.y;
    o4.z = dz * rs * gg.z + bb.z;
    o4.w = dw * rs * gg.w + bb.w;
    ((float4*)(out + (size_t)row * HIDDEN))[tid] = o4;
}

// ---------------------------------------------------------------------------
extern "C" void kernel_launch(void* const* d_in, const int* in_sizes, int n_in,
                              void* d_out, int out_size)
{
    const float* x  = (const float*)d_in[0];
    const int*   am = (const int*)d_in[1];
    const float* Wq = (const float*)d_in[2];  const float* bq = (const float*)d_in[3];
    const float* Wk = (const float*)d_in[4];  const float* bk = (const float*)d_in[5];
    const float* Wv = (const float*)d_in[6];  const float* bv = (const float*)d_in[7];
    const float* Wo = (const float*)d_in[8];  const float* bo = (const float*)d_in[9];
    const float* lg = (const float*)d_in[10]; const float* lb = (const float*)d_in[11];

    float* out = (float*)d_out;
    float* sc  = out + (size_t)ROWS * HIDDEN;   // scores follow `out` in the tuple

    qkv_gemm<<<dim3(8, 32, 3), 256>>>(x, Wq, bq, Wk, bk, Wv, bv);
    scores_kernel<<<dim3(32, 32, 32), 256>>>(am, sc);
    stats_kernel<<<SCROWS, 256>>>(sc);
    ctx_kernel<<<dim3(32, 32), 256>>>(sc);
    proj_gemm<<<dim3(8, 32), 256>>>(Wo, bo, x);
    ln_kernel<<<ROWS, 256>>>(lg, lb, out);
}

// round 3
// speedup vs baseline: 1.0014x; 1.0012x over previous
#include <cuda_runtime.h>

#define HIDDEN 1024
#define HEADS 16
#define HDIM 64
#define BATCH 2
#define SEQ 2048
#define ROWS (BATCH*SEQ)          // 4096
#define BH (BATCH*HEADS)          // 32
#define SCROWS (BH*SEQ)           // 65536
#define NEGV -1.0e9f

typedef unsigned long long ull;

// Packed f32x2 FMA (sm_103a FFMA2 — ptxas never auto-fuses; PTX-only path)
__device__ __forceinline__ void ffma2(ull& d, ull a, ull b) {
    asm("fma.rn.f32x2 %0, %1, %2, %3;" : "=l"(d) : "l"(a), "l"(b), "l"(d));
}
__device__ __forceinline__ ull pack2dup(float x) {
    ull r; asm("mov.b64 %0, {%1, %1};" : "=l"(r) : "f"(x)); return r;
}
__device__ __forceinline__ float2 unpack2(ull v) {
    float2 r; asm("mov.b64 {%0, %1}, %2;" : "=f"(r.x), "=f"(r.y) : "l"(v)); return r;
}

// Scratch (allocation-free rule: __device__ globals)
__device__ float g_q[BH*SEQ*HDIM];
__device__ float g_k[BH*SEQ*HDIM];
__device__ float g_v[BH*SEQ*HDIM];
__device__ float g_ctx[ROWS*HIDDEN];
__device__ float g_y[ROWS*HIDDEN];
__device__ float g_rmax[SCROWS];
__device__ float g_rinv[SCROWS];

// ---------------------------------------------------------------------------
// QKV projection: C = x @ W + b, scattered to [B,H,S,D]. 128x128x8 SGEMM,
// inner product in packed f32x2.
// ---------------------------------------------------------------------------
__global__ __launch_bounds__(256) void qkv_gemm(
    const float* __restrict__ x,
    const float* __restrict__ Wq, const float* __restrict__ bq,
    const float* __restrict__ Wk, const float* __restrict__ bk,
    const float* __restrict__ Wv, const float* __restrict__ bv)
{
    const float* W; const float* bias; float* out;
    if (blockIdx.z == 0)      { W = Wq; bias = bq; out = g_q; }
    else if (blockIdx.z == 1) { W = Wk; bias = bk; out = g_k; }
    else                      { W = Wv; bias = bv; out = g_v; }

    __shared__ float As[8][128];
    __shared__ float Bs[8][128];
    const int tid = threadIdx.x;
    const int tx = tid & 15, ty = tid >> 4;
    const int m0 = blockIdx.y * 128, n0 = blockIdx.x * 128;
    const int arow = tid >> 1, acol = (tid & 1) * 4;
    const int brow = tid >> 5, bcol = (tid & 31) * 4;

    ull acc2[8][4];
#pragma unroll
    for (int i = 0; i < 8; i++)
#pragma unroll
        for (int j = 0; j < 4; j++) acc2[i][j] = 0ull;

    for (int k0 = 0; k0 < HIDDEN; k0 += 8) {
        float4 a = *(const float4*)&x[(size_t)(m0 + arow) * HIDDEN + k0 + acol];
        As[acol + 0][arow] = a.x; As[acol + 1][arow] = a.y;
        As[acol + 2][arow] = a.z; As[acol + 3][arow] = a.w;
        *(float4*)&Bs[brow][bcol] =
            *(const float4*)&W[(size_t)(k0 + brow) * HIDDEN + n0 + bcol];
        __syncthreads();
#pragma unroll
        for (int kk = 0; kk < 8; kk++) {
            const ulonglong2* bp = (const ulonglong2*)&Bs[kk][tx * 8];
            ulonglong2 bA = bp[0], bB = bp[1];
            float4 a0 = *(const float4*)&As[kk][ty * 8];
            float4 a1 = *(const float4*)&As[kk][ty * 8 + 4];
            float ra[8] = {a0.x, a0.y, a0.z, a0.w, a1.x, a1.y, a1.z, a1.w};
#pragma unroll
            for (int i = 0; i < 8; i++) {
                ull ad = pack2dup(ra[i]);
                ffma2(acc2[i][0], ad, bA.x);
                ffma2(acc2[i][1], ad, bA.y);
                ffma2(acc2[i][2], ad, bB.x);
                ffma2(acc2[i][3], ad, bB.y);
            }
        }
        __syncthreads();
    }

#pragma unroll
    for (int i = 0; i < 8; i++) {
        int row = m0 + ty * 8 + i;
        int b = row >> 11, s = row & (SEQ - 1);
#pragma unroll
        for (int j4 = 0; j4 < 2; j4++) {
            int col = n0 + tx * 8 + j4 * 4;
            int h = col >> 6, d = col & 63;
            float2 p0 = unpack2(acc2[i][j4*2 + 0]);
            float2 p1 = unpack2(acc2[i][j4*2 + 1]);
            float4 v;
            v.x = p0.x + bias[col+0];
            v.y = p0.y + bias[col+1];
            v.z = p1.x + bias[col+2];
            v.w = p1.y + bias[col+3];
            *(float4*)&out[(((size_t)(b*HEADS + h))*SEQ + s)*HDIM + d] = v;
        }
    }
}

// ---------------------------------------------------------------------------
// Output projection + residual: g_y = g_ctx @ Wo + bo + x  (f32x2 inner)
// ---------------------------------------------------------------------------
__global__ __launch_bounds__(256) void proj_gemm(
    const float* __restrict__ Wo, const float* __restrict__ bo,
    const float* __restrict__ x)
{
    __shared__ float As[8][128];
    __shared__ float Bs[8][128];
    const int tid = threadIdx.x;
    const int tx = tid & 15, ty = tid >> 4;
    const int m0 = blockIdx.y * 128, n0 = blockIdx.x * 128;
    const int arow = tid >> 1, acol = (tid & 1) * 4;
    const int brow = tid >> 5, bcol = (tid & 31) * 4;

    ull acc2[8][4];
#pragma unroll
    for (int i = 0; i < 8; i++)
#pragma unroll
        for (int j = 0; j < 4; j++) acc2[i][j] = 0ull;

    for (int k0 = 0; k0 < HIDDEN; k0 += 8) {
        float4 a = *(const float4*)&g_ctx[(size_t)(m0 + arow) * HIDDEN + k0 + acol];
        As[acol + 0][arow] = a.x; As[acol + 1][arow] = a.y;
        As[acol + 2][arow] = a.z; As[acol + 3][arow] = a.w;
        *(float4*)&Bs[brow][bcol] =
            *(const float4*)&Wo[(size_t)(k0 + brow) * HIDDEN + n0 + bcol];
        __syncthreads();
#pragma unroll
        for (int kk = 0; kk < 8; kk++) {
            const ulonglong2* bp = (const ulonglong2*)&Bs[kk][tx * 8];
            ulonglong2 bA = bp[0], bB = bp[1];
            float4 a0 = *(const float4*)&As[kk][ty * 8];
            float4 a1 = *(const float4*)&As[kk][ty * 8 + 4];
            float ra[8] = {a0.x, a0.y, a0.z, a0.w, a1.x, a1.y, a1.z, a1.w};
#pragma unroll
            for (int i = 0; i < 8; i++) {
                ull ad = pack2dup(ra[i]);
                ffma2(acc2[i][0], ad, bA.x);
                ffma2(acc2[i][1], ad, bA.y);
                ffma2(acc2[i][2], ad, bB.x);
                ffma2(acc2[i][3], ad, bB.y);
            }
        }
        __syncthreads();
    }

#pragma unroll
    for (int i = 0; i < 8; i++) {
        int row = m0 + ty * 8 + i;
#pragma unroll
        for (int j4 = 0; j4 < 2; j4++) {
            int col = n0 + tx * 8 + j4 * 4;
            float4 xv = *(const float4*)&x[(size_t)row * HIDDEN + col];
            float4 bv = *(const float4*)&bo[col];
            float2 p0 = unpack2(acc2[i][j4*2 + 0]);
            float2 p1 = unpack2(acc2[i][j4*2 + 1]);
            float4 v;
            v.x = p0.x + bv.x + xv.x;
            v.y = p0.y + bv.y + xv.y;
            v.z = p1.x + bv.z + xv.z;
            v.w = p1.y + bv.w + xv.w;
            *(float4*)&g_y[(size_t)row * HIDDEN + col] = v;
        }
    }
}

// ---------------------------------------------------------------------------
// scores = (Q @ K^T)/8, masked, written to output. 64x64 tile per block.
// f32x2 inner product.
// ---------------------------------------------------------------------------
__global__ __launch_bounds__(256) void scores_kernel(
    const int* __restrict__ am, float* __restrict__ sc_out)
{
    __shared__ float QsT[64][64];
    __shared__ float KsT[64][64];
    const int tid = threadIdx.x;
    const int tx = tid & 15, ty = tid >> 4;
    const int k0 = blockIdx.x * 64, q0 = blockIdx.y * 64;
    const int bh = blockIdx.z;
    const float* qp = g_q + (size_t)bh * SEQ * HDIM;
    const float* kp = g_k + (size_t)bh * SEQ * HDIM;

#pragma unroll
    for (int it = 0; it < 4; it++) {
        int idx = it * 256 + tid;
        int d = idx & 63, rg = idx >> 6;
        float4 qv, kv;
        qv.x = qp[(size_t)(q0 + rg*4 + 0) * HDIM + d];
        qv.y = qp[(size_t)(q0 + rg*4 + 1) * HDIM + d];
        qv.z = qp[(size_t)(q0 + rg*4 + 2) * HDIM + d];
        qv.w = qp[(size_t)(q0 + rg*4 + 3) * HDIM + d];
        kv.x = kp[(size_t)(k0 + rg*4 + 0) * HDIM + d];
        kv.y = kp[(size_t)(k0 + rg*4 + 1) * HDIM + d];
        kv.z = kp[(size_t)(k0 + rg*4 + 2) * HDIM + d];
        kv.w = kp[(size_t)(k0 + rg*4 + 3) * HDIM + d];
        *(float4*)&QsT[d][4 * (rg ^ (d & 15))] = qv;
        *(float4*)&KsT[d][4 * (rg ^ (d & 15))] = kv;
    }
    __syncthreads();

    ull acc2[4][2];
#pragma unroll
    for (int i = 0; i < 4; i++) { acc2[i][0] = 0ull; acc2[i][1] = 0ull; }

#pragma unroll
    for (int d = 0; d < 64; d++) {
        float4 a = *(const float4*)&QsT[d][4 * (ty ^ (d & 15))];
        ulonglong2 b2 = *(const ulonglong2*)&KsT[d][4 * (tx ^ (d & 15))];
        float ra[4] = {a.x, a.y, a.z, a.w};
#pragma unroll
        for (int i = 0; i < 4; i++) {
            ull ad = pack2dup(ra[i]);
            ffma2(acc2[i][0], ad, b2.x);
            ffma2(acc2[i][1], ad, b2.y);
        }
    }

    const int b_ = bh >> 4;
#pragma unroll
    for (int i = 0; i < 4; i++) {
        int q = q0 + ty * 4 + i;
        int kk = k0 + tx * 4;
        int4 m4 = *(const int4*)&am[((size_t)b_ * SEQ + q) * SEQ + kk];
        float2 p0 = unpack2(acc2[i][0]);
        float2 p1 = unpack2(acc2[i][1]);
        float4 v;
        v.x = m4.x ? p0.x * 0.125f : NEGV;
        v.y = m4.y ? p0.y * 0.125f : NEGV;
        v.z = m4.z ? p1.x * 0.125f : NEGV;
        v.w = m4.w ? p1.y * 0.125f : NEGV;
        *(float4*)&sc_out[((size_t)bh * SEQ + q) * SEQ + kk] = v;
    }
}

// ---------------------------------------------------------------------------
// Per-row softmax stats: rowmax and 1/sum(exp(s-max)) over 2048 elements.
// ---------------------------------------------------------------------------
__global__ __launch_bounds__(256) void stats_kernel(const float* __restrict__ sc)
{
    const int r = blockIdx.x;
    const float4* p = (const float4*)(sc + (size_t)r * SEQ);
    const int tid = threadIdx.x;
    __shared__ float red[8];

    float4 a = p[tid];
    float4 b = p[tid + 256];
    float m = fmaxf(fmaxf(fmaxf(a.x, a.y), fmaxf(a.z, a.w)),
                    fmaxf(fmaxf(b.x, b.y), fmaxf(b.z, b.w)));
#pragma unroll
    for (int o = 16; o; o >>= 1) m = fmaxf(m, __shfl_xor_sync(0xffffffffu, m, o));
    if ((tid & 31) == 0) red[tid >> 5] = m;
    __syncthreads();
    if (tid < 32) {
        float t = (tid < 8) ? red[tid] : -3.4e38f;
#pragma unroll
        for (int o = 4; o; o >>= 1) t = fmaxf(t, __shfl_xor_sync(0xffffffffu, t, o));
        if (tid == 0) red[0] = t;
    }
    __syncthreads();
    m = red[0];
    __syncthreads();

    float s = __expf(a.x - m) + __expf(a.y - m) + __expf(a.z - m) + __expf(a.w - m)
            + __expf(b.x - m) + __expf(b.y - m) + __expf(b.z - m) + __expf(b.w - m);
#pragma unroll
    for (int o = 16; o; o >>= 1) s += __shfl_xor_sync(0xffffffffu, s, o);
    if ((tid & 31) == 0) red[tid >> 5] = s;
    __syncthreads();
    if (tid < 32) {
        float t = (tid < 8) ? red[tid] : 0.f;
#pragma unroll
        for (int o = 4; o; o >>= 1) t += __shfl_xor_sync(0xffffffffu, t, o);
        if (tid == 0) { g_rmax[r] = m; g_rinv[r] = 1.f / t; }
    }
}

// ---------------------------------------------------------------------------
// ctx = softmax(scores) @ V, probs computed on the fly; ctx stored [B,S,HIDDEN].
// f32x2 inner product.
// ---------------------------------------------------------------------------
__global__ __launch_bounds__(256) void ctx_kernel(const float* __restrict__ sc)
{
    __shared__ float PsT[64][64];
    __shared__ float Vs[64][64];
    const int tid = threadIdx.x;
    const int tx = tid & 15, ty = tid >> 4;
    const int q0 = blockIdx.x * 64;
    const int bh = blockIdx.y;
    const int b_ = bh >> 4, h = bh & 15;
    const float* vp = g_v + (size_t)bh * SEQ * HDIM;
    const float* scp = sc + (size_t)bh * SEQ * SEQ;

    ull acc2[4][2];
#pragma unroll
    for (int i = 0; i < 4; i++) { acc2[i][0] = 0ull; acc2[i][1] = 0ull; }

    for (int kk0 = 0; kk0 < SEQ; kk0 += 64) {
#pragma unroll
        for (int it = 0; it < 4; it++) {
            int idx = it * 256 + tid;
            int kl = idx & 63, qg = idx >> 6;
            int qr = q0 + qg * 4;
            float4 pv;
            pv.x = __expf(scp[(size_t)(qr+0)*SEQ + kk0 + kl] - g_rmax[bh*SEQ + qr+0]) * g_rinv[bh*SEQ + qr+0];
            pv.y = __expf(scp[(size_t)(qr+1)*SEQ + kk0 + kl] - g_rmax[bh*SEQ + qr+1]) * g_rinv[bh*SEQ + qr+1];
            pv.z = __expf(scp[(size_t)(qr+2)*SEQ + kk0 + kl] - g_rmax[bh*SEQ + qr+2]) * g_rinv[bh*SEQ + qr+2];
            pv.w = __expf(scp[(size_t)(qr+3)*SEQ + kk0 + kl] - g_rmax[bh*SEQ + qr+3]) * g_rinv[bh*SEQ + qr+3];
            *(float4*)&PsT[kl][4 * (qg ^ (kl & 15))] = pv;
        }
#pragma unroll
        for (int it = 0; it < 4; it++) {
            int idx = it * 256 + tid;
            int kr = idx >> 4, c4 = idx & 15;
            *(float4*)&Vs[kr][c4 * 4] =
                *(const float4*)&vp[(size_t)(kk0 + kr) * HDIM + c4 * 4];
        }
        __syncthreads();
#pragma unroll
        for (int k = 0; k < 64; k++) {
            float4 a = *(const float4*)&PsT[k][4 * (ty ^ (k & 15))];
            ulonglong2 b2 = *(const ulonglong2*)&Vs[k][tx * 4];
            float ra[4] = {a.x, a.y, a.z, a.w};
#pragma unroll
            for (int i = 0; i < 4; i++) {
                ull ad = pack2dup(ra[i]);
                ffma2(acc2[i][0], ad, b2.x);
                ffma2(acc2[i][1], ad, b2.y);
            }
        }
        __syncthreads();
    }

#pragma unroll
    for (int i = 0; i < 4; i++) {
        int q = q0 + ty * 4 + i;
        float2 p0 = unpack2(acc2[i][0]);
        float2 p1 = unpack2(acc2[i][1]);
        float4 v = {p0.x, p0.y, p1.x, p1.y};
        *(float4*)&g_ctx[((size_t)(b_ * SEQ + q)) * HIDDEN + h * HDIM + tx * 4] = v;
    }
}

// ---------------------------------------------------------------------------
// LayerNorm over last dim of g_y -> out
// ---------------------------------------------------------------------------
__global__ __launch_bounds__(256) void ln_kernel(
    const float* __restrict__ gamma, const float* __restrict__ beta,
    float* __restrict__ out)
{
    const int row = blockIdx.x;
    const int tid = threadIdx.x;
    __shared__ float red[8];
    const float4* p = (const float4*)(g_y + (size_t)row * HIDDEN);
    float4 v = p[tid];

    float s = v.x + v.y + v.z + v.w;
#pragma unroll
    for (int o = 16; o; o >>= 1) s += __shfl_xor_sync(0xffffffffu, s, o);
    if ((tid & 31) == 0) red[tid >> 5] = s;
    __syncthreads();
    if (tid < 32) {
        float t = (tid < 8) ? red[tid] : 0.f;
#pragma unroll
        for (int o = 4; o; o >>= 1) t += __shfl_xor_sync(0xffffffffu, t, o);
        if (tid == 0) red[0] = t;
    }
    __syncthreads();
    float mu = red[0] * (1.f / HIDDEN);
    __syncthreads();

    float dx = v.x - mu, dy = v.y - mu, dz = v.z - mu, dw = v.w - mu;
    float s2 = dx*dx + dy*dy + dz*dz + dw*dw;
#pragma unroll
    for (int o = 16; o; o >>= 1) s2 += __shfl_xor_sync(0xffffffffu, s2, o);
    if ((tid & 31) == 0) red[tid >> 5] = s2;
    __syncthreads();
    if (tid < 32) {
        float t = (tid < 8) ? red[tid] : 0.f;
#pragma unroll
        for (int o = 4; o; o >>= 1) t += __shfl_xor_sync(0xffffffffu, t, o);
        if (tid == 0) red[0] = t;
    }
    __syncthreads();
    float var = red[0] * (1.f / HIDDEN);
    float rs = rsqrtf(var + 1e-12f);

    float4 gg = ((const float4*)gamma)[tid];
    float4 bb = ((const float4*)beta)[tid];
    float4 o4;
    o4.x = dx * rs * gg.x + bb.x;
    o4.y = dy * rs * gg.y + bb.y;
    o4.z = dz * rs * gg.z + bb.z;
    o4.w = dw * rs * gg.w + bb.w;
    ((float4*)(out + (size_t)row * HIDDEN))[tid] = o4;
}

// ---------------------------------------------------------------------------
extern "C" void kernel_launch(void* const* d_in, const int* in_sizes, int n_in,
                              void* d_out, int out_size)
{
    const float* x  = (const float*)d_in[0];
    const int*   am = (const int*)d_in[1];
    const float* Wq = (const float*)d_in[2];  const float* bq = (const float*)d_in[3];
    const float* Wk = (const float*)d_in[4];  const float* bk = (const float*)d_in[5];
    const float* Wv = (const float*)d_in[6];  const float* bv = (const float*)d_in[7];
    const float* Wo = (const float*)d_in[8];  const float* bo = (const float*)d_in[9];
    const float* lg = (const float*)d_in[10]; const float* lb = (const float*)d_in[11];

    float* out = (float*)d_out;
    float* sc  = out + (size_t)ROWS * HIDDEN;   // scores follow `out` in the tuple

    qkv_gemm<<<dim3(8, 32, 3), 256>>>(x, Wq, bq, Wk, bk, Wv, bv);
    scores_kernel<<<dim3(32, 32, 32), 256>>>(am, sc);
    stats_kernel<<<SCROWS, 256>>>(sc);
    ctx_kernel<<<dim3(32, 32), 256>>>(sc);
    proj_gemm<<<dim3(8, 32), 256>>>(Wo, bo, x);
    ln_kernel<<<ROWS, 256>>>(lg, lb, out);
}

// round 5
// speedup vs baseline: 2.0341x; 2.0314x over previous
#include <cuda_runtime.h>
#include <cuda_fp16.h>
#include <cstdint>

#define HIDDEN 1024
#define HEADS 16
#define HDIM 64
#define BATCH 2
#define SEQ 2048
#define ROWS (BATCH*SEQ)          // 4096
#define BH (BATCH*HEADS)          // 32
#define SCROWS (BH*SEQ)           // 65536
#define NEGV -1.0e9f
#define PADK 72                   // padded smem row stride (halves)

// ---------------- scratch (allocation-free rule) ----------------
__device__ __half g_wth[4*HIDDEN*HIDDEN];   // W^T hi [w][n][k]
__device__ __half g_wtl[4*HIDDEN*HIDDEN];   // W^T lo
__device__ __half g_xh[ROWS*HIDDEN];
__device__ __half g_xl[ROWS*HIDDEN];
__device__ __half g_qh[BH*SEQ*HDIM];
__device__ __half g_ql[BH*SEQ*HDIM];
__device__ __half g_kh[BH*SEQ*HDIM];
__device__ __half g_kl[BH*SEQ*HDIM];
__device__ __half g_vh[BH*SEQ*HDIM];
__device__ __half g_vl[BH*SEQ*HDIM];
__device__ __half g_vth[BH*HDIM*SEQ];       // V^T [bh][d][s]
__device__ __half g_vtl[BH*HDIM*SEQ];
__device__ __half g_ctxh[ROWS*HIDDEN];
__device__ __half g_ctxl[ROWS*HIDDEN];
__device__ float g_y[ROWS*HIDDEN];
__device__ float g_rmax[SCROWS];
__device__ float g_rinv[SCROWS];

#define SMEM_G 73728   // 4 tiles of 128 x PADK halves
#define SMEM_C 55296   // ctx: A 2x(128xPADK) + B 2x(64xPADK)

// ---------------- helpers ----------------
__device__ __forceinline__ void mma16816(float* c, const uint32_t* a, const uint32_t* b) {
    asm volatile(
        "mma.sync.aligned.m16n8k16.row.col.f32.f16.f16.f32 "
        "{%0,%1,%2,%3}, {%4,%5,%6,%7}, {%8,%9}, {%0,%1,%2,%3};\n"
        : "+f"(c[0]), "+f"(c[1]), "+f"(c[2]), "+f"(c[3])
        : "r"(a[0]), "r"(a[1]), "r"(a[2]), "r"(a[3]), "r"(b[0]), "r"(b[1]));
}

__device__ __forceinline__ void splith2(float a, float b, uint32_t& hi, uint32_t& lo) {
    __half ah = __float2half_rn(a), bh = __float2half_rn(b);
    __half al = __float2half_rn(a - __half2float(ah));
    __half bl = __float2half_rn(b - __half2float(bh));
    __half2 h = __halves2half2(ah, bh), l = __halves2half2(al, bl);
    hi = *(uint32_t*)&h; lo = *(uint32_t*)&l;
}

// load a [128 x 64] half tile (row-major, stride lda) into padded smem
__device__ __forceinline__ void ldtile128(__half* dst, const __half* src, int lda, int tid) {
#pragma unroll
    for (int it = 0; it < 4; it++) {
        int idx = it * 256 + tid;
        int r = idx >> 3, j = idx & 7;
        *(uint4*)(dst + r * PADK + j * 8) = *(const uint4*)(src + (size_t)r * lda + j * 8);
    }
}

// One k16 MMA step over a warp tile: 2 m-frags x NI n-frags, 3 split passes.
template<int NI>
__device__ __forceinline__ void mma_k16(
    const __half* Ah, const __half* Al, const __half* Bh, const __half* Bl,
    int lane, int wm, int wn, int kk, float (*c)[NI][4])
{
    const int gid = lane >> 2, tig = lane & 3;
    uint32_t ah[2][4], al[2][4];
#pragma unroll
    for (int mi = 0; mi < 2; mi++) {
        const __half* p = Ah + (wm*32 + mi*16 + gid) * PADK + kk*16 + tig*2;
        const __half* q = Al + (wm*32 + mi*16 + gid) * PADK + kk*16 + tig*2;
        ah[mi][0] = *(const uint32_t*)p;
        ah[mi][1] = *(const uint32_t*)(p + 8*PADK);
        ah[mi][2] = *(const uint32_t*)(p + 8);
        ah[mi][3] = *(const uint32_t*)(p + 8*PADK + 8);
        al[mi][0] = *(const uint32_t*)q;
        al[mi][1] = *(const uint32_t*)(q + 8*PADK);
        al[mi][2] = *(const uint32_t*)(q + 8);
        al[mi][3] = *(const uint32_t*)(q + 8*PADK + 8);
    }
#pragma unroll
    for (int ni = 0; ni < NI; ni++) {
        const __half* pb = Bh + (wn*NI*8 + ni*8 + gid) * PADK + kk*16 + tig*2;
        const __half* pl = Bl + (wn*NI*8 + ni*8 + gid) * PADK + kk*16 + tig*2;
        uint32_t bh[2] = { *(const uint32_t*)pb, *(const uint32_t*)(pb + 8) };
        uint32_t bl[2] = { *(const uint32_t*)pl, *(const uint32_t*)(pl + 8) };
#pragma unroll
        for (int mi = 0; mi < 2; mi++) {
            mma16816(c[mi][ni], ah[mi], bh);
            mma16816(c[mi][ni], al[mi], bh);
            mma16816(c[mi][ni], ah[mi], bl);
        }
    }
}

// ---------------------------------------------------------------------------
// Prep: transpose + fp16-split weights: g_wt*[w][n][k] = W[k][n]
// ---------------------------------------------------------------------------
__global__ __launch_bounds__(256) void wsplit_kernel(
    const float* __restrict__ Wq, const float* __restrict__ Wk,
    const float* __restrict__ Wv, const float* __restrict__ Wo)
{
    __shared__ float t[32][33];
    const int w = blockIdx.z;
    const float* W = (w == 0) ? Wq : (w == 1) ? Wk : (w == 2) ? Wv : Wo;
    const int n0 = blockIdx.x * 32, k0 = blockIdx.y * 32;
    const int tid = threadIdx.x;
    {
        int kr = tid >> 3, nc = (tid & 7) * 4;
        float4 a = *(const float4*)(W + (size_t)(k0 + kr) * HIDDEN + n0 + nc);
        t[kr][nc] = a.x; t[kr][nc+1] = a.y; t[kr][nc+2] = a.z; t[kr][nc+3] = a.w;
    }
    __syncthreads();
    {
        int nr = tid >> 3, kc = (tid & 7) * 4;
        uint32_t h2[2], l2[2];
        splith2(t[kc][nr],   t[kc+1][nr], h2[0], l2[0]);
        splith2(t[kc+2][nr], t[kc+3][nr], h2[1], l2[1]);
        size_t idx = (size_t)w * HIDDEN * HIDDEN + (size_t)(n0 + nr) * HIDDEN + k0 + kc;
        *(uint2*)(g_wth + idx) = *(uint2*)h2;
        *(uint2*)(g_wtl + idx) = *(uint2*)l2;
    }
}

__global__ __launch_bounds__(256) void xsplit_kernel(const float* __restrict__ x)
{
    int i = blockIdx.x * 256 + threadIdx.x;
    float4 a = ((const float4*)x)[i];
    uint32_t h2[2], l2[2];
    splith2(a.x, a.y, h2[0], l2[0]);
    splith2(a.z, a.w, h2[1], l2[1]);
    ((uint2*)g_xh)[i] = *(uint2*)h2;
    ((uint2*)g_xl)[i] = *(uint2*)l2;
}

// ---------------------------------------------------------------------------
// QKV projection (HMMA): out split fp16, scattered to [bh][s][d]
// ---------------------------------------------------------------------------
__global__ __launch_bounds__(256) void qkv_hmma(
    const float* __restrict__ bq, const float* __restrict__ bk,
    const float* __restrict__ bv)
{
    extern __shared__ char smraw[];
    __half* sAh = (__half*)smraw;
    __half* sAl = sAh + 128*PADK;
    __half* sBh = sAl + 128*PADK;
    __half* sBl = sBh + 128*PADK;
    const int tid = threadIdx.x, lane = tid & 31, w = tid >> 5;
    const int wm = w >> 1, wn = w & 1;
    const int z = blockIdx.z;
    const int m0 = blockIdx.y * 128, n0 = blockIdx.x * 128;

    const __half* wth = g_wth + (size_t)z * HIDDEN * HIDDEN;
    const __half* wtl = g_wtl + (size_t)z * HIDDEN * HIDDEN;

    float c[2][8][4];
#pragma unroll
    for (int i = 0; i < 2; i++)
#pragma unroll
        for (int j = 0; j < 8; j++)
#pragma unroll
            for (int k = 0; k < 4; k++) c[i][j][k] = 0.f;

    for (int k0 = 0; k0 < HIDDEN; k0 += 64) {
        __syncthreads();
        ldtile128(sAh, g_xh + (size_t)m0 * HIDDEN + k0, HIDDEN, tid);
        ldtile128(sAl, g_xl + (size_t)m0 * HIDDEN + k0, HIDDEN, tid);
        ldtile128(sBh, wth + (size_t)n0 * HIDDEN + k0, HIDDEN, tid);
        ldtile128(sBl, wtl + (size_t)n0 * HIDDEN + k0, HIDDEN, tid);
        __syncthreads();
#pragma unroll
        for (int kk = 0; kk < 4; kk++)
            mma_k16<8>(sAh, sAl, sBh, sBl, lane, wm, wn, kk, c);
    }

    const int gid = lane >> 2, tig = lane & 3;
    const float* bias = (z == 0) ? bq : (z == 1) ? bk : bv;
    __half* oh = (z == 0) ? g_qh : (z == 1) ? g_kh : g_vh;
    __half* ol = (z == 0) ? g_ql : (z == 1) ? g_kl : g_vl;
#pragma unroll
    for (int mi = 0; mi < 2; mi++)
#pragma unroll
    for (int hf = 0; hf < 2; hf++) {
        int row = m0 + wm*32 + mi*16 + hf*8 + gid;
        int bb = row >> 11, s = row & (SEQ - 1);
#pragma unroll
        for (int ni = 0; ni < 8; ni++) {
            int col = n0 + wn*64 + ni*8 + tig*2;
            int h = col >> 6, d = col & 63;
            float v0 = c[mi][ni][hf*2]     + bias[col];
            float v1 = c[mi][ni][hf*2 + 1] + bias[col + 1];
            uint32_t hi, lo; splith2(v0, v1, hi, lo);
            size_t o = ((size_t)(bb * HEADS + h) * SEQ + s) * HDIM + d;
            *(uint32_t*)(oh + o) = hi;
            *(uint32_t*)(ol + o) = lo;
        }
    }
}

// ---------------------------------------------------------------------------
// V transpose: [bh][s][d] -> [bh][d][s]
// ---------------------------------------------------------------------------
__global__ __launch_bounds__(256) void vtrans_kernel()
{
    __shared__ __half t[64][80];
    const int s0 = blockIdx.x * 64, bh = blockIdx.y;
    const int tid = threadIdx.x;
#pragma unroll
    for (int rep = 0; rep < 2; rep++) {
        const __half* src = rep ? g_vl : g_vh;
        __half* dst = rep ? g_vtl : g_vth;
        {
            int r = tid >> 2, j = (tid & 3) * 16;
            const uint4* sp = (const uint4*)(src + ((size_t)bh * SEQ + s0 + r) * HDIM + j);
            *(uint4*)&t[r][j] = sp[0];
            *(uint4*)&t[r][j + 8] = sp[1];
        }
        __syncthreads();
        {
            int d = tid >> 2, i0 = (tid & 3) * 16;
            __half tmp[16];
#pragma unroll
            for (int i = 0; i < 16; i++) tmp[i] = t[i0 + i][d];
            uint4* dp = (uint4*)(dst + ((size_t)bh * HDIM + d) * SEQ + s0 + i0);
            dp[0] = ((uint4*)tmp)[0];
            dp[1] = ((uint4*)tmp)[1];
        }
        __syncthreads();
    }
}

// ---------------------------------------------------------------------------
// scores = masked (Q K^T)/8 (HMMA) + fused online softmax stats
// grid (16 q-tiles, 32 bh)
// ---------------------------------------------------------------------------
__global__ __launch_bounds__(256) void scores_hmma(
    const int* __restrict__ am, float* __restrict__ sc)
{
    extern __shared__ char smraw[];
    __half* sAh = (__half*)smraw;
    __half* sAl = sAh + 128*PADK;
    __half* sBh = sAl + 128*PADK;
    __half* sBl = sBh + 128*PADK;
    const int tid = threadIdx.x, lane = tid & 31, w = tid >> 5;
    const int wm = w >> 1, wn = w & 1;
    const int gid = lane >> 2, tig = lane & 3;
    const int q0 = blockIdx.x * 128, bh = blockIdx.y;
    const int b = bh >> 4;

    ldtile128(sAh, g_qh + ((size_t)bh * SEQ + q0) * HDIM, HDIM, tid);
    ldtile128(sAl, g_ql + ((size_t)bh * SEQ + q0) * HDIM, HDIM, tid);

    float mrun[4], srun[4];
#pragma unroll
    for (int i = 0; i < 4; i++) { mrun[i] = -1e30f; srun[i] = 0.f; }

    for (int t16 = 0; t16 < 16; t16++) {
        const int k0t = t16 * 128;
        __syncthreads();
        ldtile128(sBh, g_kh + ((size_t)bh * SEQ + k0t) * HDIM, HDIM, tid);
        ldtile128(sBl, g_kl + ((size_t)bh * SEQ + k0t) * HDIM, HDIM, tid);
        __syncthreads();

        float c[2][8][4];
#pragma unroll
        for (int i = 0; i < 2; i++)
#pragma unroll
            for (int j = 0; j < 8; j++)
#pragma unroll
                for (int k = 0; k < 4; k++) c[i][j][k] = 0.f;
#pragma unroll
        for (int kk = 0; kk < 4; kk++)
            mma_k16<8>(sAh, sAl, sBh, sBl, lane, wm, wn, kk, c);

#pragma unroll
        for (int mi = 0; mi < 2; mi++)
#pragma unroll
        for (int hf = 0; hf < 2; hf++) {
            const int slot = mi*2 + hf;
            const int row = q0 + wm*32 + mi*16 + hf*8 + gid;
            const int* mrow = am + ((size_t)b * SEQ + row) * SEQ;
            float* orow = sc + ((size_t)bh * SEQ + row) * SEQ;
            float tv[16];
#pragma unroll
            for (int ni = 0; ni < 8; ni++) {
                int colk = k0t + wn*64 + ni*8 + tig*2;
                int2 mm = *(const int2*)(mrow + colk);
                float v0 = mm.x ? c[mi][ni][hf*2]     * 0.125f : NEGV;
                float v1 = mm.y ? c[mi][ni][hf*2 + 1] * 0.125f : NEGV;
                float2 st; st.x = v0; st.y = v1;
                *(float2*)(orow + colk) = st;
                tv[2*ni] = v0; tv[2*ni + 1] = v1;
            }
            float tm = tv[0];
#pragma unroll
            for (int i = 1; i < 16; i++) tm = fmaxf(tm, tv[i]);
            float mn = fmaxf(mrun[slot], tm);
            float sa = 0.f;
#pragma unroll
            for (int i = 0; i < 16; i++) sa += __expf(tv[i] - mn);
            srun[slot] = srun[slot] * __expf(mrun[slot] - mn) + sa;
            mrun[slot] = mn;
        }
    }

    // reduce: quad (tig bits), then across the 2 k-warps (wn) via smem
    __syncthreads();
    float2* red = (float2*)smraw;
#pragma unroll
    for (int slot = 0; slot < 4; slot++) {
        float m = mrun[slot], s = srun[slot];
#pragma unroll
        for (int o = 1; o <= 2; o <<= 1) {
            float mo = __shfl_xor_sync(0xffffffffu, m, o);
            float so = __shfl_xor_sync(0xffffffffu, s, o);
            float mn = fmaxf(m, mo);
            s = s * __expf(m - mn) + so * __expf(mo - mn);
            m = mn;
        }
        if (tig == 0) {
            int loc = wm*32 + (slot >> 1)*16 + (slot & 1)*8 + gid;
            red[wn*128 + loc] = make_float2(m, s);
        }
    }
    __syncthreads();
    if (tid < 128) {
        float2 p0 = red[tid], p1 = red[128 + tid];
        float mn = fmaxf(p0.x, p1.x);
        float ss = p0.y * __expf(p0.x - mn) + p1.y * __expf(p1.x - mn);
        g_rmax[bh * SEQ + q0 + tid] = mn;
        g_rinv[bh * SEQ + q0 + tid] = 1.f / ss;
    }
}

// ---------------------------------------------------------------------------
// ctx = softmax(scores) @ V (HMMA); probs generated on the fly, split fp16 out
// grid (16 q-tiles, 32 bh)
// ---------------------------------------------------------------------------
__global__ __launch_bounds__(256) void ctx_hmma(const float* __restrict__ sc)
{
    extern __shared__ char smraw[];
    __half* pAh = (__half*)smraw;
    __half* pAl = pAh + 128*PADK;
    __half* vBh = pAl + 128*PADK;
    __half* vBl = vBh + 64*PADK;
    const int tid = threadIdx.x, lane = tid & 31, w = tid >> 5;
    const int wm = w >> 1, wn = w & 1;
    const int gid = lane >> 2, tig = lane & 3;
    const int q0 = blockIdx.x * 128, bh = blockIdx.y;
    const int b = bh >> 4, h = bh & 15;

    const int row_t = tid >> 1, colh = (tid & 1) * 32;
    const float rm = g_rmax[bh * SEQ + q0 + row_t];
    const float ri = g_rinv[bh * SEQ + q0 + row_t];
    const float* srow = sc + ((size_t)bh * SEQ + q0 + row_t) * SEQ + colh;

    float c[2][4][4];
#pragma unroll
    for (int i = 0; i < 2; i++)
#pragma unroll
        for (int j = 0; j < 4; j++)
#pragma unroll
            for (int k = 0; k < 4; k++) c[i][j][k] = 0.f;

    for (int ch = 0; ch < 32; ch++) {
        const int k0 = ch * 64;
        __syncthreads();
        // A tile: probs (fp16 split) for this 128x64 chunk
        {
            float pv[32];
#pragma unroll
            for (int i = 0; i < 8; i++)
                ((float4*)pv)[i] = *(const float4*)(srow + k0 + i*4);
            __half* dh = pAh + row_t * PADK + colh;
            __half* dl = pAl + row_t * PADK + colh;
#pragma unroll
            for (int i = 0; i < 16; i++) {
                float p0 = __expf(pv[2*i]     - rm) * ri;
                float p1 = __expf(pv[2*i + 1] - rm) * ri;
                uint32_t hi, lo; splith2(p0, p1, hi, lo);
                *(uint32_t*)(dh + 2*i) = hi;
                *(uint32_t*)(dl + 2*i) = lo;
            }
        }
        // B tile: V^T [64 d][64 s]
#pragma unroll
        for (int it = 0; it < 2; it++) {
            int idx = it * 256 + tid;
            int r = idx >> 3, j = idx & 7;
            *(uint4*)(vBh + r*PADK + j*8) =
                *(const uint4*)(g_vth + ((size_t)bh * HDIM + r) * SEQ + k0 + j*8);
            *(uint4*)(vBl + r*PADK + j*8) =
                *(const uint4*)(g_vtl + ((size_t)bh * HDIM + r) * SEQ + k0 + j*8);
        }
        __syncthreads();
#pragma unroll
        for (int kk = 0; kk < 4; kk++)
            mma_k16<4>(pAh, pAl, vBh, vBl, lane, wm, wn, kk, c);
    }

#pragma unroll
    for (int mi = 0; mi < 2; mi++)
#pragma unroll
    for (int hf = 0; hf < 2; hf++) {
        int q = q0 + wm*32 + mi*16 + hf*8 + gid;
#pragma unroll
        for (int ni = 0; ni < 4; ni++) {
            int d = wn*32 + ni*8 + tig*2;
            uint32_t hi, lo;
            splith2(c[mi][ni][hf*2], c[mi][ni][hf*2 + 1], hi, lo);
            size_t o = ((size_t)(b * SEQ + q)) * HIDDEN + h * HDIM + d;
            *(uint32_t*)(g_ctxh + o) = hi;
            *(uint32_t*)(g_ctxl + o) = lo;
        }
    }
}

// ---------------------------------------------------------------------------
// Out projection + residual (HMMA): g_y = ctx @ Wo + bo + x
// ---------------------------------------------------------------------------
__global__ __launch_bounds__(256) void proj_hmma(
    const float* __restrict__ bo, const float* __restrict__ x)
{
    extern __shared__ char smraw[];
    __half* sAh = (__half*)smraw;
    __half* sAl = sAh + 128*PADK;
    __half* sBh = sAl + 128*PADK;
    __half* sBl = sBh + 128*PADK;
    const int tid = threadIdx.x, lane = tid & 31, w = tid >> 5;
    const int wm = w >> 1, wn = w & 1;
    const int m0 = blockIdx.y * 128, n0 = blockIdx.x * 128;

    const __half* wth = g_wth + (size_t)3 * HIDDEN * HIDDEN;
    const __half* wtl = g_wtl + (size_t)3 * HIDDEN * HIDDEN;

    float c[2][8][4];
#pragma unroll
    for (int i = 0; i < 2; i++)
#pragma unroll
        for (int j = 0; j < 8; j++)
#pragma unroll
            for (int k = 0; k < 4; k++) c[i][j][k] = 0.f;

    for (int k0 = 0; k0 < HIDDEN; k0 += 64) {
        __syncthreads();
        ldtile128(sAh, g_ctxh + (size_t)m0 * HIDDEN + k0, HIDDEN, tid);
        ldtile128(sAl, g_ctxl + (size_t)m0 * HIDDEN + k0, HIDDEN, tid);
        ldtile128(sBh, wth + (size_t)n0 * HIDDEN + k0, HIDDEN, tid);
        ldtile128(sBl, wtl + (size_t)n0 * HIDDEN + k0, HIDDEN, tid);
        __syncthreads();
#pragma unroll
        for (int kk = 0; kk < 4; kk++)
            mma_k16<8>(sAh, sAl, sBh, sBl, lane, wm, wn, kk, c);
    }

    const int gid = lane >> 2, tig = lane & 3;
#pragma unroll
    for (int mi = 0; mi < 2; mi++)
#pragma unroll
    for (int hf = 0; hf < 2; hf++) {
        int row = m0 + wm*32 + mi*16 + hf*8 + gid;
#pragma unroll
        for (int ni = 0; ni < 8; ni++) {
            int col = n0 + wn*64 + ni*8 + tig*2;
            float2 xv = *(const float2*)(x + (size_t)row * HIDDEN + col);
            float2 st;
            st.x = c[mi][ni][hf*2]     + bo[col]     + xv.x;
            st.y = c[mi][ni][hf*2 + 1] + bo[col + 1] + xv.y;
            *(float2*)(g_y + (size_t)row * HIDDEN + col) = st;
        }
    }
}

// ---------------------------------------------------------------------------
// LayerNorm over last dim of g_y -> out
// ---------------------------------------------------------------------------
__global__ __launch_bounds__(256) void ln_kernel(
    const float* __restrict__ gamma, const float* __restrict__ beta,
    float* __restrict__ out)
{
    const int row = blockIdx.x;
    const int tid = threadIdx.x;
    __shared__ float red[8];
    const float4* p = (const float4*)(g_y + (size_t)row * HIDDEN);
    float4 v = p[tid];

    float s = v.x + v.y + v.z + v.w;
#pragma unroll
    for (int o = 16; o; o >>= 1) s += __shfl_xor_sync(0xffffffffu, s, o);
    if ((tid & 31) == 0) red[tid >> 5] = s;
    __syncthreads();
    if (tid < 32) {
        float t = (tid < 8) ? red[tid] : 0.f;
#pragma unroll
        for (int o = 4; o; o >>= 1) t += __shfl_xor_sync(0xffffffffu, t, o);
        if (tid == 0) red[0] = t;
    }
    __syncthreads();
    float mu = red[0] * (1.f / HIDDEN);
    __syncthreads();

    float dx = v.x - mu, dy = v.y - mu, dz = v.z - mu, dw = v.w - mu;
    float s2 = dx*dx + dy*dy + dz*dz + dw*dw;
#pragma unroll
    for (int o = 16; o; o >>= 1) s2 += __shfl_xor_sync(0xffffffffu, s2, o);
    if ((tid & 31) == 0) red[tid >> 5] = s2;
    __syncthreads();
    if (tid < 32) {
        float t = (tid < 8) ? red[tid] : 0.f;
#pragma unroll
        for (int o = 4; o; o >>= 1) t += __shfl_xor_sync(0xffffffffu, t, o);
        if (tid == 0) red[0] = t;
    }
    __syncthreads();
    float var = red[0] * (1.f / HIDDEN);
    float rs = rsqrtf(var + 1e-12f);

    float4 gg = ((const float4*)gamma)[tid];
    float4 bb = ((const float4*)beta)[tid];
    float4 o4;
    o4.x = dx * rs * gg.x + bb.x;
    o4.y = dy * rs * gg.y + bb.y;
    o4.z = dz * rs * gg.z + bb.z;
    o4.w = dw * rs * gg.w + bb.w;
    ((float4*)(out + (size_t)row * HIDDEN))[tid] = o4;
}

// ---------------------------------------------------------------------------
extern "C" void kernel_launch(void* const* d_in, const int* in_sizes, int n_in,
                              void* d_out, int out_size)
{
    const float* x  = (const float*)d_in[0];
    const int*   am = (const int*)d_in[1];
    const float* Wq = (const float*)d_in[2];  const float* bq = (const float*)d_in[3];
    const float* Wk = (const float*)d_in[4];  const float* bk = (const float*)d_in[5];
    const float* Wv = (const float*)d_in[6];  const float* bv = (const float*)d_in[7];
    const float* Wo = (const float*)d_in[8];  const float* bo = (const float*)d_in[9];
    const float* lg = (const float*)d_in[10]; const float* lb = (const float*)d_in[11];

    float* out = (float*)d_out;
    float* sc  = out + (size_t)ROWS * HIDDEN;   // scores follow `out` in the tuple

    cudaFuncSetAttribute(qkv_hmma,    cudaFuncAttributeMaxDynamicSharedMemorySize, SMEM_G);
    cudaFuncSetAttribute(scores_hmma, cudaFuncAttributeMaxDynamicSharedMemorySize, SMEM_G);
    cudaFuncSetAttribute(ctx_hmma,    cudaFuncAttributeMaxDynamicSharedMemorySize, SMEM_C);
    cudaFuncSetAttribute(proj_hmma,   cudaFuncAttributeMaxDynamicSharedMemorySize, SMEM_G);

    wsplit_kernel<<<dim3(32, 32, 4), 256>>>(Wq, Wk, Wv, Wo);
    xsplit_kernel<<<4096, 256>>>(x);
    qkv_hmma<<<dim3(8, 32, 3), 256, SMEM_G>>>(bq, bk, bv);
    vtrans_kernel<<<dim3(32, 32), 256>>>();
    scores_hmma<<<dim3(16, 32), 256, SMEM_G>>>(am, sc);
    ctx_hmma<<<dim3(16, 32), 256, SMEM_C>>>(sc);
    proj_hmma<<<dim3(8, 32), 256, SMEM_G>>>(bo, x);
    ln_kernel<<<ROWS, 256>>>(lg, lb, out);
}

// round 6
// speedup vs baseline: 2.2086x; 1.0858x over previous
#include <cuda_runtime.h>
#include <cuda_fp16.h>
#include <cstdint>

#define HIDDEN 1024
#define HEADS 16
#define HDIM 64
#define BATCH 2
#define SEQ 2048
#define ROWS (BATCH*SEQ)          // 4096
#define BH (BATCH*HEADS)          // 32
#define NEGV -1.0e9f
#define PADK 72                   // padded smem row stride (halves)

// ---------------- scratch (allocation-free rule) ----------------
__device__ __half g_wth[4*HIDDEN*HIDDEN];   // W^T hi [w][n][k]
__device__ __half g_wtl[4*HIDDEN*HIDDEN];   // W^T lo
__device__ __half g_xh[ROWS*HIDDEN];
__device__ __half g_xl[ROWS*HIDDEN];
__device__ __half g_qh[BH*SEQ*HDIM];
__device__ __half g_ql[BH*SEQ*HDIM];
__device__ __half g_kh[BH*SEQ*HDIM];
__device__ __half g_kl[BH*SEQ*HDIM];
__device__ __half g_vh[BH*SEQ*HDIM];
__device__ __half g_vl[BH*SEQ*HDIM];
__device__ __half g_vth[BH*HDIM*SEQ];       // V^T [bh][d][s]
__device__ __half g_vtl[BH*HDIM*SEQ];
__device__ __half g_ctxh[ROWS*HIDDEN];
__device__ __half g_ctxl[ROWS*HIDDEN];
__device__ float g_y[ROWS*HIDDEN];

#define SMEM_G 73728    // gemm kernels: 4 tiles of 128 x PADK halves
#define SMEM_F 110592   // fused attn: (2*128 + 4*64 + 2*128) * PADK * 2B

// ---------------- helpers ----------------
__device__ __forceinline__ void mma16816(float* c, const uint32_t* a, const uint32_t* b) {
    asm volatile(
        "mma.sync.aligned.m16n8k16.row.col.f32.f16.f16.f32 "
        "{%0,%1,%2,%3}, {%4,%5,%6,%7}, {%8,%9}, {%0,%1,%2,%3};\n"
        : "+f"(c[0]), "+f"(c[1]), "+f"(c[2]), "+f"(c[3])
        : "r"(a[0]), "r"(a[1]), "r"(a[2]), "r"(a[3]), "r"(b[0]), "r"(b[1]));
}

__device__ __forceinline__ void splith2(float a, float b, uint32_t& hi, uint32_t& lo) {
    __half ah = __float2half_rn(a), bh = __float2half_rn(b);
    __half al = __float2half_rn(a - __half2float(ah));
    __half bl = __float2half_rn(b - __half2float(bh));
    __half2 h = __halves2half2(ah, bh), l = __halves2half2(al, bl);
    hi = *(uint32_t*)&h; lo = *(uint32_t*)&l;
}

// load [128 x 64] / [64 x 64] half tiles (row-major, stride lda) into padded smem
__device__ __forceinline__ void ldtile128(__half* dst, const __half* src, int lda, int tid) {
#pragma unroll
    for (int it = 0; it < 4; it++) {
        int idx = it * 256 + tid;
        int r = idx >> 3, j = idx & 7;
        *(uint4*)(dst + r * PADK + j * 8) = *(const uint4*)(src + (size_t)r * lda + j * 8);
    }
}
__device__ __forceinline__ void ldtile64(__half* dst, const __half* src, int lda, int tid) {
#pragma unroll
    for (int it = 0; it < 2; it++) {
        int idx = it * 256 + tid;
        int r = idx >> 3, j = idx & 7;
        *(uint4*)(dst + r * PADK + j * 8) = *(const uint4*)(src + (size_t)r * lda + j * 8);
    }
}

// 128x128 GEMM helper: 2 m-frags x 8 n-frags per warp (wm 0-3, wn 0-1), K=64
__device__ __forceinline__ void mma_k16x8(
    const __half* Ah, const __half* Al, const __half* Bh, const __half* Bl,
    int lane, int wm, int wn, int kk, float (*c)[8][4])
{
    const int gid = lane >> 2, tig = lane & 3;
    uint32_t ah[2][4], al[2][4];
#pragma unroll
    for (int mi = 0; mi < 2; mi++) {
        const __half* p = Ah + (wm*32 + mi*16 + gid) * PADK + kk*16 + tig*2;
        const __half* q = Al + (wm*32 + mi*16 + gid) * PADK + kk*16 + tig*2;
        ah[mi][0] = *(const uint32_t*)p;
        ah[mi][1] = *(const uint32_t*)(p + 8*PADK);
        ah[mi][2] = *(const uint32_t*)(p + 8);
        ah[mi][3] = *(const uint32_t*)(p + 8*PADK + 8);
        al[mi][0] = *(const uint32_t*)q;
        al[mi][1] = *(const uint32_t*)(q + 8*PADK);
        al[mi][2] = *(const uint32_t*)(q + 8);
        al[mi][3] = *(const uint32_t*)(q + 8*PADK + 8);
    }
#pragma unroll
    for (int ni = 0; ni < 8; ni++) {
        const __half* pb = Bh + (wn*64 + ni*8 + gid) * PADK + kk*16 + tig*2;
        const __half* pl = Bl + (wn*64 + ni*8 + gid) * PADK + kk*16 + tig*2;
        uint32_t bh[2] = { *(const uint32_t*)pb, *(const uint32_t*)(pb + 8) };
        uint32_t bl[2] = { *(const uint32_t*)pl, *(const uint32_t*)(pl + 8) };
#pragma unroll
        for (int mi = 0; mi < 2; mi++) {
            mma16816(c[mi][ni], ah[mi], bh);
            mma16816(c[mi][ni], al[mi], bh);
            mma16816(c[mi][ni], ah[mi], bl);
        }
    }
}

// fused-attn helper: warp tile 16(m) x 64(n), K=64, 3 split passes, accumulate
__device__ __forceinline__ void mma_w16(
    const __half* Ah, const __half* Al, const __half* Bh, const __half* Bl,
    int lane, int w, float (*c)[4])
{
    const int gid = lane >> 2, tig = lane & 3;
#pragma unroll
    for (int kk = 0; kk < 4; kk++) {
        const __half* p = Ah + (w*16 + gid) * PADK + kk*16 + tig*2;
        const __half* q = Al + (w*16 + gid) * PADK + kk*16 + tig*2;
        uint32_t ah[4] = { *(const uint32_t*)p, *(const uint32_t*)(p + 8*PADK),
                           *(const uint32_t*)(p + 8), *(const uint32_t*)(p + 8*PADK + 8) };
        uint32_t al[4] = { *(const uint32_t*)q, *(const uint32_t*)(q + 8*PADK),
                           *(const uint32_t*)(q + 8), *(const uint32_t*)(q + 8*PADK + 8) };
#pragma unroll
        for (int ni = 0; ni < 8; ni++) {
            const __half* pb = Bh + (ni*8 + gid) * PADK + kk*16 + tig*2;
            const __half* pl = Bl + (ni*8 + gid) * PADK + kk*16 + tig*2;
            uint32_t bh[2] = { *(const uint32_t*)pb, *(const uint32_t*)(pb + 8) };
            uint32_t bl[2] = { *(const uint32_t*)pl, *(const uint32_t*)(pl + 8) };
            mma16816(c[ni], ah, bh);
            mma16816(c[ni], al, bh);
            mma16816(c[ni], ah, bl);
        }
    }
}

// ---------------------------------------------------------------------------
// Prep: transpose + fp16-split weights: g_wt*[w][n][k] = W[k][n]
// ---------------------------------------------------------------------------
__global__ __launch_bounds__(256) void wsplit_kernel(
    const float* __restrict__ Wq, const float* __restrict__ Wk,
    const float* __restrict__ Wv, const float* __restrict__ Wo)
{
    __shared__ float t[32][33];
    const int w = blockIdx.z;
    const float* W = (w == 0) ? Wq : (w == 1) ? Wk : (w == 2) ? Wv : Wo;
    const int n0 = blockIdx.x * 32, k0 = blockIdx.y * 32;
    const int tid = threadIdx.x;
    {
        int kr = tid >> 3, nc = (tid & 7) * 4;
        float4 a = *(const float4*)(W + (size_t)(k0 + kr) * HIDDEN + n0 + nc);
        t[kr][nc] = a.x; t[kr][nc+1] = a.y; t[kr][nc+2] = a.z; t[kr][nc+3] = a.w;
    }
    __syncthreads();
    {
        int nr = tid >> 3, kc = (tid & 7) * 4;
        uint32_t h2[2], l2[2];
        splith2(t[kc][nr],   t[kc+1][nr], h2[0], l2[0]);
        splith2(t[kc+2][nr], t[kc+3][nr], h2[1], l2[1]);
        size_t idx = (size_t)w * HIDDEN * HIDDEN + (size_t)(n0 + nr) * HIDDEN + k0 + kc;
        *(uint2*)(g_wth + idx) = *(uint2*)h2;
        *(uint2*)(g_wtl + idx) = *(uint2*)l2;
    }
}

__global__ __launch_bounds__(256) void xsplit_kernel(const float* __restrict__ x)
{
    int i = blockIdx.x * 256 + threadIdx.x;
    float4 a = ((const float4*)x)[i];
    uint32_t h2[2], l2[2];
    splith2(a.x, a.y, h2[0], l2[0]);
    splith2(a.z, a.w, h2[1], l2[1]);
    ((uint2*)g_xh)[i] = *(uint2*)h2;
    ((uint2*)g_xl)[i] = *(uint2*)l2;
}

// ---------------------------------------------------------------------------
// QKV projection (HMMA): out split fp16, scattered to [bh][s][d]
// ---------------------------------------------------------------------------
__global__ __launch_bounds__(256) void qkv_hmma(
    const float* __restrict__ bq, const float* __restrict__ bk,
    const float* __restrict__ bv)
{
    extern __shared__ char smraw[];
    __half* sAh = (__half*)smraw;
    __half* sAl = sAh + 128*PADK;
    __half* sBh = sAl + 128*PADK;
    __half* sBl = sBh + 128*PADK;
    const int tid = threadIdx.x, lane = tid & 31, w = tid >> 5;
    const int wm = w >> 1, wn = w & 1;
    const int z = blockIdx.z;
    const int m0 = blockIdx.y * 128, n0 = blockIdx.x * 128;

    const __half* wth = g_wth + (size_t)z * HIDDEN * HIDDEN;
    const __half* wtl = g_wtl + (size_t)z * HIDDEN * HIDDEN;

    float c[2][8][4];
#pragma unroll
    for (int i = 0; i < 2; i++)
#pragma unroll
        for (int j = 0; j < 8; j++)
#pragma unroll
            for (int k = 0; k < 4; k++) c[i][j][k] = 0.f;

    for (int k0 = 0; k0 < HIDDEN; k0 += 64) {
        __syncthreads();
        ldtile128(sAh, g_xh + (size_t)m0 * HIDDEN + k0, HIDDEN, tid);
        ldtile128(sAl, g_xl + (size_t)m0 * HIDDEN + k0, HIDDEN, tid);
        ldtile128(sBh, wth + (size_t)n0 * HIDDEN + k0, HIDDEN, tid);
        ldtile128(sBl, wtl + (size_t)n0 * HIDDEN + k0, HIDDEN, tid);
        __syncthreads();
#pragma unroll
        for (int kk = 0; kk < 4; kk++)
            mma_k16x8(sAh, sAl, sBh, sBl, lane, wm, wn, kk, c);
    }

    const int gid = lane >> 2, tig = lane & 3;
    const float* bias = (z == 0) ? bq : (z == 1) ? bk : bv;
    __half* oh = (z == 0) ? g_qh : (z == 1) ? g_kh : g_vh;
    __half* ol = (z == 0) ? g_ql : (z == 1) ? g_kl : g_vl;
#pragma unroll
    for (int mi = 0; mi < 2; mi++)
#pragma unroll
    for (int hf = 0; hf < 2; hf++) {
        int row = m0 + wm*32 + mi*16 + hf*8 + gid;
        int bb = row >> 11, s = row & (SEQ - 1);
#pragma unroll
        for (int ni = 0; ni < 8; ni++) {
            int col = n0 + wn*64 + ni*8 + tig*2;
            int h = col >> 6, d = col & 63;
            float v0 = c[mi][ni][hf*2]     + bias[col];
            float v1 = c[mi][ni][hf*2 + 1] + bias[col + 1];
            uint32_t hi, lo; splith2(v0, v1, hi, lo);
            size_t o = ((size_t)(bb * HEADS + h) * SEQ + s) * HDIM + d;
            *(uint32_t*)(oh + o) = hi;
            *(uint32_t*)(ol + o) = lo;
        }
    }
}

// ---------------------------------------------------------------------------
// V transpose: [bh][s][d] -> [bh][d][s]
// ---------------------------------------------------------------------------
__global__ __launch_bounds__(256) void vtrans_kernel()
{
    __shared__ __half t[64][80];
    const int s0 = blockIdx.x * 64, bh = blockIdx.y;
    const int tid = threadIdx.x;
#pragma unroll
    for (int rep = 0; rep < 2; rep++) {
        const __half* src = rep ? g_vl : g_vh;
        __half* dst = rep ? g_vtl : g_vth;
        {
            int r = tid >> 2, j = (tid & 3) * 16;
            const uint4* sp = (const uint4*)(src + ((size_t)bh * SEQ + s0 + r) * HDIM + j);
            *(uint4*)&t[r][j] = sp[0];
            *(uint4*)&t[r][j + 8] = sp[1];
        }
        __syncthreads();
        {
            int d = tid >> 2, i0 = (tid & 3) * 16;
            __half tmp[16];
#pragma unroll
            for (int i = 0; i < 16; i++) tmp[i] = t[i0 + i][d];
            uint4* dp = (uint4*)(dst + ((size_t)bh * HDIM + d) * SEQ + s0 + i0);
            dp[0] = ((uint4*)tmp)[0];
            dp[1] = ((uint4*)tmp)[1];
        }
        __syncthreads();
    }
}

// ---------------------------------------------------------------------------
// Fused attention: scores (masked, written to output) + online softmax +
// P@V with running rescale. Grid (16 q-tiles, 32 bh), 8 warps x 16 q-rows.
// ---------------------------------------------------------------------------
__global__ __launch_bounds__(256) void attn_fused(
    const int* __restrict__ am, float* __restrict__ sc)
{
    extern __shared__ char smraw[];
    __half* sQh = (__half*)smraw;           // 128 x PADK
    __half* sQl = sQh + 128*PADK;
    __half* sKh = sQl + 128*PADK;           // 64 x PADK
    __half* sKl = sKh + 64*PADK;
    __half* sVh = sKl + 64*PADK;            // V^T 64 x PADK
    __half* sVl = sVh + 64*PADK;
    __half* sPh = sVl + 64*PADK;            // 128 x PADK
    __half* sPl = sPh + 128*PADK;

    const int tid = threadIdx.x, lane = tid & 31, w = tid >> 5;
    const int gid = lane >> 2, tig = lane & 3;
    const int q0 = blockIdx.x * 128, bh = blockIdx.y;
    const int b = bh >> 4, h = bh & 15;

    ldtile128(sQh, g_qh + ((size_t)bh * SEQ + q0) * HDIM, HDIM, tid);
    ldtile128(sQl, g_ql + ((size_t)bh * SEQ + q0) * HDIM, HDIM, tid);

    const int r0 = q0 + w*16 + gid;                 // slot-0 row; slot-1 = +8
    const int* mrow0 = am + ((size_t)b * SEQ + r0) * SEQ;
    const int* mrow1 = mrow0 + 8 * SEQ;
    float* orow0 = sc + ((size_t)bh * SEQ + r0) * SEQ;
    float* orow1 = orow0 + 8 * SEQ;

    float m_run[2] = {-1e30f, -1e30f}, s_run[2] = {0.f, 0.f};
    float co[8][4];
#pragma unroll
    for (int i = 0; i < 8; i++)
#pragma unroll
        for (int j = 0; j < 4; j++) co[i][j] = 0.f;

    const __half* kh = g_kh + (size_t)bh * SEQ * HDIM;
    const __half* kl = g_kl + (size_t)bh * SEQ * HDIM;
    const __half* vth = g_vth + (size_t)bh * HDIM * SEQ;
    const __half* vtl = g_vtl + (size_t)bh * HDIM * SEQ;

    for (int ch = 0; ch < 32; ch++) {
        const int k0 = ch * 64;
        __syncthreads();
        ldtile64(sKh, kh + (size_t)k0 * HDIM, HDIM, tid);
        ldtile64(sKl, kl + (size_t)k0 * HDIM, HDIM, tid);
        ldtile64(sVh, vth + k0, SEQ, tid);
        ldtile64(sVl, vtl + k0, SEQ, tid);
        __syncthreads();

        float cs[8][4];
#pragma unroll
        for (int i = 0; i < 8; i++)
#pragma unroll
            for (int j = 0; j < 4; j++) cs[i][j] = 0.f;
        mma_w16(sQh, sQl, sKh, sKl, lane, w, cs);

        // mask + scale + store scores; collect per-row values
        float tv0[16], tv1[16];
#pragma unroll
        for (int ni = 0; ni < 8; ni++) {
            int col = k0 + ni*8 + tig*2;
            int2 mm0 = *(const int2*)(mrow0 + col);
            int2 mm1 = *(const int2*)(mrow1 + col);
            float v00 = mm0.x ? cs[ni][0] * 0.125f : NEGV;
            float v01 = mm0.y ? cs[ni][1] * 0.125f : NEGV;
            float v10 = mm1.x ? cs[ni][2] * 0.125f : NEGV;
            float v11 = mm1.y ? cs[ni][3] * 0.125f : NEGV;
            *(float2*)(orow0 + col) = make_float2(v00, v01);
            *(float2*)(orow1 + col) = make_float2(v10, v11);
            tv0[2*ni] = v00; tv0[2*ni+1] = v01;
            tv1[2*ni] = v10; tv1[2*ni+1] = v11;
        }
        // row max (16 local values, then quad reduce over tig)
        float tm0 = tv0[0], tm1 = tv1[0];
#pragma unroll
        for (int i = 1; i < 16; i++) { tm0 = fmaxf(tm0, tv0[i]); tm1 = fmaxf(tm1, tv1[i]); }
#pragma unroll
        for (int o = 1; o <= 2; o <<= 1) {
            tm0 = fmaxf(tm0, __shfl_xor_sync(0xffffffffu, tm0, o));
            tm1 = fmaxf(tm1, __shfl_xor_sync(0xffffffffu, tm1, o));
        }
        float mn0 = fmaxf(m_run[0], tm0), mn1 = fmaxf(m_run[1], tm1);
        float sf0 = __expf(m_run[0] - mn0), sf1 = __expf(m_run[1] - mn1);

        // exp + local sum; store unnormalized P (fp16 split) to smem
        float sa0 = 0.f, sa1 = 0.f;
#pragma unroll
        for (int i = 0; i < 16; i++) {
            tv0[i] = __expf(tv0[i] - mn0); sa0 += tv0[i];
            tv1[i] = __expf(tv1[i] - mn1); sa1 += tv1[i];
        }
#pragma unroll
        for (int o = 1; o <= 2; o <<= 1) {
            sa0 += __shfl_xor_sync(0xffffffffu, sa0, o);
            sa1 += __shfl_xor_sync(0xffffffffu, sa1, o);
        }
        s_run[0] = s_run[0] * sf0 + sa0; m_run[0] = mn0;
        s_run[1] = s_run[1] * sf1 + sa1; m_run[1] = mn1;

        // rescale running output accumulator
#pragma unroll
        for (int ni = 0; ni < 8; ni++) {
            co[ni][0] *= sf0; co[ni][1] *= sf0;
            co[ni][2] *= sf1; co[ni][3] *= sf1;
        }
        // write P rows (warp-private)
        {
            __half* d0h = sPh + (w*16 + gid) * PADK + tig*2;
            __half* d0l = sPl + (w*16 + gid) * PADK + tig*2;
#pragma unroll
            for (int ni = 0; ni < 8; ni++) {
                uint32_t hi, lo;
                splith2(tv0[2*ni], tv0[2*ni+1], hi, lo);
                *(uint32_t*)(d0h + ni*8) = hi;
                *(uint32_t*)(d0l + ni*8) = lo;
                splith2(tv1[2*ni], tv1[2*ni+1], hi, lo);
                *(uint32_t*)(d0h + 8*PADK + ni*8) = hi;
                *(uint32_t*)(d0l + 8*PADK + ni*8) = lo;
            }
        }
        __syncwarp();
        mma_w16(sPh, sPl, sVh, sVl, lane, w, co);   // accumulate into co
    }

    // finalize: normalize and write ctx (fp16 split) to [B,S,HIDDEN]
    float ri0 = 1.f / s_run[0], ri1 = 1.f / s_run[1];
    size_t ob0 = ((size_t)(b * SEQ + r0)) * HIDDEN + h * HDIM;
    size_t ob1 = ob0 + (size_t)8 * HIDDEN;
#pragma unroll
    for (int ni = 0; ni < 8; ni++) {
        int d = ni*8 + tig*2;
        uint32_t hi, lo;
        splith2(co[ni][0] * ri0, co[ni][1] * ri0, hi, lo);
        *(uint32_t*)(g_ctxh + ob0 + d) = hi;
        *(uint32_t*)(g_ctxl + ob0 + d) = lo;
        splith2(co[ni][2] * ri1, co[ni][3] * ri1, hi, lo);
        *(uint32_t*)(g_ctxh + ob1 + d) = hi;
        *(uint32_t*)(g_ctxl + ob1 + d) = lo;
    }
}

// ---------------------------------------------------------------------------
// Out projection + residual (HMMA): g_y = ctx @ Wo + bo + x
// ---------------------------------------------------------------------------
__global__ __launch_bounds__(256) void proj_hmma(
    const float* __restrict__ bo, const float* __restrict__ x)
{
    extern __shared__ char smraw[];
    __half* sAh = (__half*)smraw;
    __half* sAl = sAh + 128*PADK;
    __half* sBh = sAl + 128*PADK;
    __half* sBl = sBh + 128*PADK;
    const int tid = threadIdx.x, lane = tid & 31, w = tid >> 5;
    const int wm = w >> 1, wn = w & 1;
    const int m0 = blockIdx.y * 128, n0 = blockIdx.x * 128;

    const __half* wth = g_wth + (size_t)3 * HIDDEN * HIDDEN;
    const __half* wtl = g_wtl + (size_t)3 * HIDDEN * HIDDEN;

    float c[2][8][4];
#pragma unroll
    for (int i = 0; i < 2; i++)
#pragma unroll
        for (int j = 0; j < 8; j++)
#pragma unroll
            for (int k = 0; k < 4; k++) c[i][j][k] = 0.f;

    for (int k0 = 0; k0 < HIDDEN; k0 += 64) {
        __syncthreads();
        ldtile128(sAh, g_ctxh + (size_t)m0 * HIDDEN + k0, HIDDEN, tid);
        ldtile128(sAl, g_ctxl + (size_t)m0 * HIDDEN + k0, HIDDEN, tid);
        ldtile128(sBh, wth + (size_t)n0 * HIDDEN + k0, HIDDEN, tid);
        ldtile128(sBl, wtl + (size_t)n0 * HIDDEN + k0, HIDDEN, tid);
        __syncthreads();
#pragma unroll
        for (int kk = 0; kk < 4; kk++)
            mma_k16x8(sAh, sAl, sBh, sBl, lane, wm, wn, kk, c);
    }

    const int gid = lane >> 2, tig = lane & 3;
#pragma unroll
    for (int mi = 0; mi < 2; mi++)
#pragma unroll
    for (int hf = 0; hf < 2; hf++) {
        int row = m0 + wm*32 + mi*16 + hf*8 + gid;
#pragma unroll
        for (int ni = 0; ni < 8; ni++) {
            int col = n0 + wn*64 + ni*8 + tig*2;
            float2 xv = *(const float2*)(x + (size_t)row * HIDDEN + col);
            float2 st;
            st.x = c[mi][ni][hf*2]     + bo[col]     + xv.x;
            st.y = c[mi][ni][hf*2 + 1] + bo[col + 1] + xv.y;
            *(float2*)(g_y + (size_t)row * HIDDEN + col) = st;
        }
    }
}

// ---------------------------------------------------------------------------
// LayerNorm over last dim of g_y -> out
// ---------------------------------------------------------------------------
__global__ __launch_bounds__(256) void ln_kernel(
    const float* __restrict__ gamma, const float* __restrict__ beta,
    float* __restrict__ out)
{
    const int row = blockIdx.x;
    const int tid = threadIdx.x;
    __shared__ float red[8];
    const float4* p = (const float4*)(g_y + (size_t)row * HIDDEN);
    float4 v = p[tid];

    float s = v.x + v.y + v.z + v.w;
#pragma unroll
    for (int o = 16; o; o >>= 1) s += __shfl_xor_sync(0xffffffffu, s, o);
    if ((tid & 31) == 0) red[tid >> 5] = s;
    __syncthreads();
    if (tid < 32) {
        float t = (tid < 8) ? red[tid] : 0.f;
#pragma unroll
        for (int o = 4; o; o >>= 1) t += __shfl_xor_sync(0xffffffffu, t, o);
        if (tid == 0) red[0] = t;
    }
    __syncthreads();
    float mu = red[0] * (1.f / HIDDEN);
    __syncthreads();

    float dx = v.x - mu, dy = v.y - mu, dz = v.z - mu, dw = v.w - mu;
    float s2 = dx*dx + dy*dy + dz*dz + dw*dw;
#pragma unroll
    for (int o = 16; o; o >>= 1) s2 += __shfl_xor_sync(0xffffffffu, s2, o);
    if ((tid & 31) == 0) red[tid >> 5] = s2;
    __syncthreads();
    if (tid < 32) {
        float t = (tid < 8) ? red[tid] : 0.f;
#pragma unroll
        for (int o = 4; o; o >>= 1) t += __shfl_xor_sync(0xffffffffu, t, o);
        if (tid == 0) red[0] = t;
    }
    __syncthreads();
    float var = red[0] * (1.f / HIDDEN);
    float rs = rsqrtf(var + 1e-12f);

    float4 gg = ((const float4*)gamma)[tid];
    float4 bb = ((const float4*)beta)[tid];
    float4 o4;
    o4.x = dx * rs * gg.x + bb.x;
    o4.y = dy * rs * gg.y + bb.y;
    o4.z = dz * rs * gg.z + bb.z;
    o4.w = dw * rs * gg.w + bb.w;
    ((float4*)(out + (size_t)row * HIDDEN))[tid] = o4;
}

// ---------------------------------------------------------------------------
extern "C" void kernel_launch(void* const* d_in, const int* in_sizes, int n_in,
                              void* d_out, int out_size)
{
    const float* x  = (const float*)d_in[0];
    const int*   am = (const int*)d_in[1];
    const float* Wq = (const float*)d_in[2];  const float* bq = (const float*)d_in[3];
    const float* Wk = (const float*)d_in[4];  const float* bk = (const float*)d_in[5];
    const float* Wv = (const float*)d_in[6];  const float* bv = (const float*)d_in[7];
    const float* Wo = (const float*)d_in[8];  const float* bo = (const float*)d_in[9];
    const float* lg = (const float*)d_in[10]; const float* lb = (const float*)d_in[11];

    float* out = (float*)d_out;
    float* sc  = out + (size_t)ROWS * HIDDEN;   // scores follow `out` in the tuple

    cudaFuncSetAttribute(qkv_hmma,   cudaFuncAttributeMaxDynamicSharedMemorySize, SMEM_G);
    cudaFuncSetAttribute(attn_fused, cudaFuncAttributeMaxDynamicSharedMemorySize, SMEM_F);
    cudaFuncSetAttribute(proj_hmma,  cudaFuncAttributeMaxDynamicSharedMemorySize, SMEM_G);

    wsplit_kernel<<<dim3(32, 32, 4), 256>>>(Wq, Wk, Wv, Wo);
    xsplit_kernel<<<4096, 256>>>(x);
    qkv_hmma<<<dim3(8, 32, 3), 256, SMEM_G>>>(bq, bk, bv);
    vtrans_kernel<<<dim3(32, 32), 256>>>();
    attn_fused<<<dim3(16, 32), 256, SMEM_F>>>(am, sc);
    proj_hmma<<<dim3(8, 32), 256, SMEM_G>>>(bo, x);
    ln_kernel<<<ROWS, 256>>>(lg, lb, out);
}